// round 13
// baseline (speedup 1.0000x reference)
#include <cuda_runtime.h>
#include <cuda_fp16.h>

// SlinkyForcePredictor — fused per-edge kernel, v12 (= v11 + 1-line fix).
// v11 failed (rel 7.5e-2): the e1 stage-3 block was missing
// fma2(GA[1][1], xc.x, GGy) -> GA[1][1]=0 -> g=sigmoid(0)=0.5 on edge-1 odd
// channels. v12 restores it. Structure unchanged from v11:
//  - GG = (K1*Wsc0@Wg, K0*Wl2_0@Wg) precomputed in pack_kernel (fp16)
//  - stage 4 eliminated; gate accumulated in stage 3 via (x0,a0) pair
//  - one contiguous uint4 weight staging; last layer stores gated y1..y3 only
// X phys layout: [x1,x2,x3,x8, x4,x5,x6,x7, x0,a0,a1,a2]; HID overlay 10/11.

#define MULC 50
#define NBC 10
#define HIDC 100
#define TE 32
#define NTHREADS 512

typedef unsigned long long u64;

struct PW {                    // packed per-layer weights
  __half Wsc[3][MULC][MULC];   // 15000
  __half Wl1[MULC][MULC];      // 5000
  __half Wl2[3][MULC][MULC];   // 15000
  __half GG[MULC][MULC][2];    // 10000  [u][v][{x0w,a0w}] (constants baked)
  float  W1[NBC][HIDC];        // 4000
  float  b1[104];              // 416
  __half W2i[50][152][2];      // 30400  [h/2][c][h&1], c=u*3+p
  __half pad2[4];              // 8 -> total 79824 (16-mult)
};
static_assert(sizeof(PW) % 16 == 0, "PW must be 16B multiple");

__device__ PW PWg[3];

struct SM {
  float X[TE][MULC][12];
  float s[TE][MULC];
  float shv[TE][12];
  float emb[TE][12];
  PW pw;
};

__device__ __forceinline__ float geluf(float x) {
  float x3 = x * x * x;
  float t = tanhf(0.7978845608028654f * (x + 0.044715f * x3));
  return 0.5f * x * (1.0f + t);
}
__device__ __forceinline__ float sigmoidf(float x) { return 1.0f / (1.0f + expf(-x)); }
__device__ __forceinline__ float siluf(float x) { return x * sigmoidf(x); }

__device__ __forceinline__ float2 ldh2(const __half* p) {
  return __half22float2(*reinterpret_cast<const __half2*>(p));
}
__device__ __forceinline__ u64 pk(float lo, float hi) {
  u64 r; asm("mov.b64 %0, {%1, %2};" : "=l"(r) : "f"(lo), "f"(hi)); return r;
}
__device__ __forceinline__ void upk(float& lo, float& hi, u64 v) {
  asm("mov.b64 {%0, %1}, %2;" : "=f"(lo), "=f"(hi) : "l"(v));
}
__device__ __forceinline__ void fma2(u64& d, u64 a, u64 b) {
  asm("fma.rn.f32x2 %0, %1, %2, %3;" : "=l"(d) : "l"(a), "l"(b), "l"(d));
}

// ---------------- pre-kernel: repack weights + fuse gate products ----------------
__global__ void pack_kernel(const float* __restrict__ Wsc_g,
                            const float* __restrict__ Wlin1_g,
                            const float* __restrict__ Wlin2_g,
                            const float* __restrict__ Wgate_g,
                            const float* __restrict__ W1_g,
                            const float* __restrict__ b1_g,
                            const float* __restrict__ W2_g)
{
  const int i = blockIdx.x;            // layer
  PW* p = &PWg[i];
  __half* d;
  d = &p->Wsc[0][0][0];
  for (int t = threadIdx.x; t < 7500; t += blockDim.x) d[t] = __float2half_rn(Wsc_g[i * 7500 + t]);
  d = &p->Wl1[0][0];
  for (int t = threadIdx.x; t < 2500; t += blockDim.x) d[t] = __float2half_rn(Wlin1_g[i * 7500 + t]);
  d = &p->Wl2[0][0][0];
  for (int t = threadIdx.x; t < 7500; t += blockDim.x) d[t] = __float2half_rn(Wlin2_g[i * 7500 + t]);
  // GG[u][v] = (K1 * sum_m Wsc0[u][m]*Wg[m][v], K0 * sum_m Wl2_0[u][m]*Wg[m][v])
  {
    const float K1 = 0.9238795325112867f * 0.1414213562373095f;   // cs/sqrt(50)
    const float K0 = 0.3826834323650898f * 0.05773502691896258f;  // cx/sqrt(300)
    const float* G = Wgate_g + i * 2500;
    for (int t = threadIdx.x; t < 2500; t += blockDim.x) {
      int u = t / 50;
      int v = t - u * 50;
      const float* A = Wsc_g + i * 7500 + u * 50;
      const float* B = Wlin2_g + i * 7500 + u * 50;
      float sx = 0.0f, sa = 0.0f;
      #pragma unroll 10
      for (int m = 0; m < 50; m++) {
        float gv = G[m * 50 + v];
        sx = fmaf(A[m], gv, sx);
        sa = fmaf(B[m], gv, sa);
      }
      p->GG[u][v][0] = __float2half_rn(K1 * sx);
      p->GG[u][v][1] = __float2half_rn(K0 * sa);
    }
  }
  float* f = &p->W1[0][0];
  for (int t = threadIdx.x; t < 1000; t += blockDim.x) f[t] = W1_g[i * 1000 + t];
  for (int t = threadIdx.x; t < 104; t += blockDim.x) p->b1[t] = (t < 100) ? b1_g[i * 100 + t] : 0.0f;
  const float* g = W2_g + i * 75000;
  for (int t = threadIdx.x; t < 15000; t += blockDim.x) {
    int h = t / 150;
    int c = t - h * 150;
    int u = c / 3;
    int pp = c - u * 3;
    p->W2i[h >> 1][c][h & 1] = __float2half_rn(g[h * 750 + u * 15 + pp]);
  }
}

// ---------------- main kernel ----------------
__global__ __launch_bounds__(NTHREADS, 1)
void slinky_kernel(const float* __restrict__ node_pos,
                   const float* __restrict__ bar_alpha,
                   const float* __restrict__ W_embed,
                   const float* __restrict__ Wout_g,
                   float* __restrict__ out)
{
  extern __shared__ __align__(16) float smem_raw[];
  SM* sm = reinterpret_cast<SM*>(smem_raw);

  const int tid = threadIdx.x;
  const int w   = tid >> 5;
  const int ln  = tid & 31;
  const int e0  = 2 * w;
  const int e1  = 2 * w + 1;
  const bool act = (ln < 25);
  const int u0 = 2 * ln;

  const float INVS50 = 0.1414213562373095f;
  const float CS = 0.9238795325112867f;
  const float CX = 0.3826834323650898f;
  const float K1 = CS * INVS50;
  const float CXK0 = CX * 0.05773502691896258f;
  const float CXK1 = CX * 0.02357022603955159f;
  const float CXK2 = CX * 0.01825741858350554f;

  // ---------------- preprocess ----------------
  {
    const int half = ln >> 4;
    const int l16 = ln & 15;
    const int le = e0 + half;
    const int eg = blockIdx.x * TE + le;
    const float* p6 = node_pos + (size_t)eg * 6;
    float ex = p6[1] - p6[0];
    float ey = p6[3] - p6[2];
    float ez = p6[5] - p6[4];
    float r = sqrtf(ex * ex + ey * ey + ez * ez);
    float inv = 1.0f / fmaxf(r, 1e-12f);
    float vx = ex * inv, vy = ey * inv, vz = ez * inv;
    if (l16 == 0) {
      const float s3 = 1.7320508075688772f;
      const float s5 = 2.23606797749979f;
      const float s15 = 3.872983346207417f;
      float* shp = sm->shv[le];
      shp[0] = 1.0f;
      shp[1] = s3 * vx;
      shp[2] = s3 * vy;
      shp[3] = s3 * vz;
      shp[4] = s15 * vx * vz;
      shp[5] = s15 * vx * vy;
      shp[6] = s5 * (vy * vy - 0.5f * (vx * vx + vz * vz));
      shp[7] = s15 * vy * vz;
      shp[8] = 0.5f * s15 * (vz * vz - vx * vx);
    }
    if (l16 < NBC) {
      const float step = 4.0f / 11.0f;
      float c = (float)(l16 + 1) * step;
      float diff = (r - c) / step;
      float up = diff + 1.0f, um = 1.0f - diff;
      float ua = (up > 0.0f) ? expf(-1.0f / up) : 0.0f;
      float ub = (um > 0.0f) ? expf(-1.0f / um) : 0.0f;
      sm->emb[le][l16] = (1.14136f * 7.3890560989306495f * 3.1622776601683795f) * ua * ub;
    }
  }
  if (act) {
    const int geb = blockIdx.x * TE;
    #pragma unroll
    for (int e = 0; e < 2; e++) {
      int le = e0 + e;
      int eg = geb + le;
      float ba_s = bar_alpha[2 * eg];
      float ba_d = bar_alpha[2 * eg + 1];
      #pragma unroll
      for (int ch = 0; ch < 2; ch++) {
        int u = u0 + ch;
        float we = W_embed[u];
        sm->s[le][u] = ba_s * we;
        float* xr = sm->X[le][u];
        #pragma unroll
        for (int k = 0; k < 8; k++) xr[k] = 0.0f;
        xr[8] = ba_d * we;                       // x0 at phys 8
      }
    }
  }

  // ---------------- layers ----------------
  for (int i = 0; i < 3; i++) {
    __syncthreads();
    // weight staging: one contiguous vector copy
    {
      const uint4* src = reinterpret_cast<const uint4*>(&PWg[i]);
      uint4* dst = reinterpret_cast<uint4*>(&sm->pw);
      for (int t = tid; t < (int)(sizeof(PW) / 16); t += NTHREADS) dst[t] = src[t];
    }
    __syncthreads();

    // ---- stage 1a: radial MLP hidden -> X slots 10/11 (h pairs) ----
    #pragma unroll
    for (int j = 0; j < 4; j++) {
      int h = ln + 32 * j;
      if (h < HIDC) {
        float a0 = 0.0f, a1 = 0.0f;
        #pragma unroll
        for (int b = 0; b < NBC; b++) {
          float w1 = sm->pw.W1[b][h];
          a0 = fmaf(sm->emb[e0][b], w1, a0);
          a1 = fmaf(sm->emb[e1][b], w1, a1);
        }
        sm->X[e0][h >> 1][10 + (h & 1)] = geluf(a0 * 0.31622776601683794f + sm->pw.b1[h]);
        sm->X[e1][h >> 1][10 + (h & 1)] = geluf(a1 * 0.31622776601683794f + sm->pw.b1[h]);
      }
    }
    __syncwarp();

    // ---- stage 1b: pairwise-h matvec (f32x2 over h parity) ----
    u64 AC0[6] = {}, AC1[6] = {};
    if (act) {
      #pragma unroll 2
      for (int h2 = 0; h2 < 50; h2++) {
        u64 H0 = *reinterpret_cast<const u64*>(&sm->X[e0][h2][10]);
        u64 H1 = *reinterpret_cast<const u64*>(&sm->X[e1][h2][10]);
        const __half* wp = &sm->pw.W2i[h2][6 * ln][0];
        #pragma unroll
        for (int j = 0; j < 6; j++) {
          float2 wj = ldh2(wp + 2 * j);
          u64 W = pk(wj.x, wj.y);
          fma2(AC0[j], H0, W);
          fma2(AC1[j], H1, W);
        }
      }
    }
    float wv[2][2][3];
    #pragma unroll
    for (int j = 0; j < 6; j++) {
      float lo, hi;
      upk(lo, hi, AC0[j]); wv[0][j / 3][j % 3] = lo + hi;
      upk(lo, hi, AC1[j]); wv[1][j / 3][j % 3] = lo + hi;
    }

    // ---- stage 2: source matvecs (packed over ch) ----
    u64 H0p = 0ull, H1p = 0ull, SC0p = 0ull, SC1p = 0ull;
    if (act) {
      #pragma unroll 5
      for (int t = 0; t < MULC; t++) {
        float s0 = sm->s[e0][t];
        float s1 = sm->s[e1][t];
        float2 wl = ldh2(&sm->pw.Wl1[t][u0]);
        float2 ws = ldh2(&sm->pw.Wsc[0][t][u0]);
        u64 WL = pk(wl.x, wl.y), WS = pk(ws.x, ws.y);
        u64 S0 = pk(s0, s0), S1 = pk(s1, s1);
        fma2(H0p, S0, WL);
        fma2(SC0p, S0, WS);
        fma2(H1p, S1, WL);
        fma2(SC1p, S1, WS);
      }
    }
    float h0a[2][2], sca[2][2];
    upk(h0a[0][0], h0a[0][1], H0p);
    upk(h0a[1][0], h0a[1][1], H1p);
    upk(sca[0][0], sca[0][1], SC0p);
    upk(sca[1][0], sca[1][1], SC1p);
    __syncwarp();
    if (act) {
      #pragma unroll
      for (int e = 0; e < 2; e++) {
        int le = e0 + e;
        #pragma unroll
        for (int ch = 0; ch < 2; ch++) {
          int u = u0 + ch;
          float h0 = h0a[e][ch] * INVS50;
          float* xr = sm->X[le][u];
          xr[9]  = h0 * wv[e][ch][0] * 0.1f;   // a0
          xr[10] = h0 * wv[e][ch][1] * 0.1f;   // a1
          xr[11] = h0 * wv[e][ch][2] * 0.1f;   // a2
          sm->s[le][u] = siluf(CS * sca[e][ch] * INVS50);
        }
      }
    }
    __syncwarp();

    // ---- stage 3 (+folded gate): pairs (x1,x2)(x3,x8)(x4,x5)(x6,x7)(x0,a0)(a1,a2) ----
    u64 A[2][2][6] = {};
    u64 GA[2][2] = {};
    if (act) {
      #pragma unroll 2
      for (int u = 0; u < MULC; u++) {
        float2 ws0 = ldh2(&sm->pw.Wsc[0][u][u0]);
        float2 ws1 = ldh2(&sm->pw.Wsc[1][u][u0]);
        float2 ws2 = ldh2(&sm->pw.Wsc[2][u][u0]);
        float2 l0 = ldh2(&sm->pw.Wl2[0][u][u0]);
        float2 l1 = ldh2(&sm->pw.Wl2[1][u][u0]);
        float2 l2 = ldh2(&sm->pw.Wl2[2][u][u0]);
        uint2 ggw = *reinterpret_cast<const uint2*>(&sm->pw.GG[u][u0][0]);
        float2 gg0 = __half22float2(*reinterpret_cast<const __half2*>(&ggw.x));
        float2 gg1 = __half22float2(*reinterpret_cast<const __half2*>(&ggw.y));
        u64 GGx = pk(gg0.x, gg0.y);
        u64 GGy = pk(gg1.x, gg1.y);
        u64 Q0x = pk(ws1.x, ws1.x);
        u64 Q1x = pk(ws1.x, ws2.x);
        u64 Q2x = pk(ws2.x, ws2.x);
        u64 Q3x = pk(ws0.x, l0.x);
        u64 Q4x = pk(l1.x, l2.x);
        u64 Q0y = pk(ws1.y, ws1.y);
        u64 Q1y = pk(ws1.y, ws2.y);
        u64 Q2y = pk(ws2.y, ws2.y);
        u64 Q3y = pk(ws0.y, l0.y);
        u64 Q4y = pk(l1.y, l2.y);
        {
          const ulonglong2* xp = reinterpret_cast<const ulonglong2*>(sm->X[e0][u]);
          ulonglong2 xa = xp[0], xb = xp[1], xc = xp[2];
          fma2(A[0][0][0], xa.x, Q0x);
          fma2(A[0][0][1], xa.y, Q1x);
          fma2(A[0][0][2], xb.x, Q2x);
          fma2(A[0][0][3], xb.y, Q2x);
          fma2(A[0][0][4], xc.x, Q3x);
          fma2(A[0][0][5], xc.y, Q4x);
          fma2(GA[0][0],   xc.x, GGx);
          fma2(A[0][1][0], xa.x, Q0y);
          fma2(A[0][1][1], xa.y, Q1y);
          fma2(A[0][1][2], xb.x, Q2y);
          fma2(A[0][1][3], xb.y, Q2y);
          fma2(A[0][1][4], xc.x, Q3y);
          fma2(A[0][1][5], xc.y, Q4y);
          fma2(GA[0][1],   xc.x, GGy);
        }
        {
          const ulonglong2* xp = reinterpret_cast<const ulonglong2*>(sm->X[e1][u]);
          ulonglong2 xa = xp[0], xb = xp[1], xc = xp[2];
          fma2(A[1][0][0], xa.x, Q0x);
          fma2(A[1][0][1], xa.y, Q1x);
          fma2(A[1][0][2], xb.x, Q2x);
          fma2(A[1][0][3], xb.y, Q2x);
          fma2(A[1][0][4], xc.x, Q3x);
          fma2(A[1][0][5], xc.y, Q4x);
          fma2(GA[1][0],   xc.x, GGx);
          fma2(A[1][1][0], xa.x, Q0y);
          fma2(A[1][1][1], xa.y, Q1y);
          fma2(A[1][1][2], xb.x, Q2y);
          fma2(A[1][1][3], xb.y, Q2y);
          fma2(A[1][1][4], xc.x, Q3y);
          fma2(A[1][1][5], xc.y, Q4y);
          fma2(GA[1][1],   xc.x, GGy);   // <-- the missing line (v11 bug)
        }
      }
    }
    __syncwarp();   // all lanes done reading X
    if (act) {
      #pragma unroll
      for (int e = 0; e < 2; e++) {
        int le = e0 + e;
        const float* shl = sm->shv[le];
        #pragma unroll
        for (int ch = 0; ch < 2; ch++) {
          int u = u0 + ch;
          float ac1, ac2, ac3, ac8, ac4, ac5, ac6, ac7, ac0, b0, b1v, b2;
          upk(ac1, ac2, A[e][ch][0]);
          upk(ac3, ac8, A[e][ch][1]);
          upk(ac4, ac5, A[e][ch][2]);
          upk(ac6, ac7, A[e][ch][3]);
          upk(ac0, b0,  A[e][ch][4]);
          upk(b1v, b2,  A[e][ch][5]);
          float glo, ghi;
          upk(glo, ghi, GA[e][ch]);
          float g = sigmoidf((glo + ghi) * INVS50);
          float x0n = K1 * ac0 + CXK0 * b0;
          float y1 = (K1 * ac1 + CXK1 * b1v * shl[1]) * g;
          float y2 = (K1 * ac2 + CXK1 * b1v * shl[2]) * g;
          float y3 = (K1 * ac3 + CXK1 * b1v * shl[3]) * g;
          float* xr = sm->X[le][u];
          if (i < 2) {
            float y4 = (K1 * ac4 + CXK2 * b2 * shl[4]) * g;
            float y5 = (K1 * ac5 + CXK2 * b2 * shl[5]) * g;
            float y6 = (K1 * ac6 + CXK2 * b2 * shl[6]) * g;
            float y7 = (K1 * ac7 + CXK2 * b2 * shl[7]) * g;
            float y8 = (K1 * ac8 + CXK2 * b2 * shl[8]) * g;
            *reinterpret_cast<float4*>(xr)     = make_float4(y1, y2, y3, y8);
            *reinterpret_cast<float4*>(xr + 4) = make_float4(y4, y5, y6, y7);
            xr[8] = siluf(x0n);
          } else {
            xr[0] = y1;
            xr[1] = y2;
            xr[2] = y3;
          }
        }
      }
    }
    __syncwarp();
  }

  // ---------------- output: gated y1..y3 at phys 0..2 ----------------
  {
    float p[2][3] = {};
    if (act) {
      float wo0 = Wout_g[u0];
      float wo1 = Wout_g[u0 + 1];
      #pragma unroll
      for (int e = 0; e < 2; e++) {
        int le = e0 + e;
        const float* r0 = sm->X[le][u0];
        const float* r1 = sm->X[le][u0 + 1];
        p[e][0] = r0[0] * wo0 + r1[0] * wo1;
        p[e][1] = r0[1] * wo0 + r1[1] * wo1;
        p[e][2] = r0[2] * wo0 + r1[2] * wo1;
      }
    }
    #pragma unroll
    for (int off = 16; off; off >>= 1) {
      #pragma unroll
      for (int e = 0; e < 2; e++) {
        p[e][0] += __shfl_xor_sync(0xffffffffu, p[e][0], off);
        p[e][1] += __shfl_xor_sync(0xffffffffu, p[e][1], off);
        p[e][2] += __shfl_xor_sync(0xffffffffu, p[e][2], off);
      }
    }
    if (ln == 0) {
      int eg0 = blockIdx.x * TE + e0;
      float* od = out + (size_t)(2 * eg0) * 3;
      od[0] = 0.0f; od[1] = 0.0f; od[2] = 0.0f;
      od[3] = p[0][0] * INVS50;
      od[4] = p[0][1] * INVS50;
      od[5] = p[0][2] * INVS50;
      od[6] = 0.0f; od[7] = 0.0f; od[8] = 0.0f;
      od[9]  = p[1][0] * INVS50;
      od[10] = p[1][1] * INVS50;
      od[11] = p[1][2] * INVS50;
    }
  }
}

extern "C" void kernel_launch(void* const* d_in, const int* in_sizes, int n_in,
                              void* d_out, int out_size) {
  const float* node_pos = (const float*)d_in[0];
  const float* bar_alpha = (const float*)d_in[1];
  const float* W_embed  = (const float*)d_in[2];
  const float* Wsc      = (const float*)d_in[3];
  const float* Wlin1    = (const float*)d_in[4];
  const float* W1       = (const float*)d_in[5];
  const float* b1       = (const float*)d_in[6];
  const float* W2       = (const float*)d_in[7];
  const float* Wlin2    = (const float*)d_in[8];
  const float* Wgate    = (const float*)d_in[9];
  const float* W_out    = (const float*)d_in[10];
  float* out = (float*)d_out;

  pack_kernel<<<3, 256>>>(Wsc, Wlin1, Wlin2, Wgate, W1, b1, W2);

  int E = in_sizes[0] / 6;
  size_t smem = sizeof(SM);
  cudaFuncSetAttribute(slinky_kernel, cudaFuncAttributeMaxDynamicSharedMemorySize, (int)smem);
  slinky_kernel<<<E / TE, NTHREADS, smem>>>(node_pos, bar_alpha, W_embed, W_out, out);
}

// round 14
// speedup vs baseline: 1.0281x; 1.0281x over previous
#include <cuda_runtime.h>
#include <cuda_fp16.h>

// SlinkyForcePredictor — fused per-edge kernel, v13.
// Base = v10 (best, 649.7us; gate fold abandoned after clean A/B showed -2%).
// v13: weight-load consolidation via pack_kernel layouts:
//  - P0/P1/P2[u][25] uint2: stage-3 weights in 3xLDS.64 (was 6xLDS.32; same wf)
//  - WQ2[t/2][25] uint4: stage-2 wl/ws for 2 t's in 1xLDS.128 (was 4xLDS.32);
//    s loaded as float2 (50->25 iters)
//  - stage-1a emb as float2
// Everything else identical to v10.
// X phys layout: [x1,x2,x3,x0,x4,x5,x6,x7,x8,a0,a1,a2]; HID overlay 10/11.

#define MULC 50
#define NBC 10
#define HIDC 100
#define TE 32
#define NTHREADS 512

typedef unsigned long long u64;

struct PW {                     // packed per-layer weights
  __half P0[50][25][4];         // 10000  {ws0x,ws0y,ws1x,ws1y} per (u, ch-pair)
  __half P1[50][25][4];         // 10000  {ws2x,ws2y,l0x,l0y}
  __half P2[50][25][4];         // 10000  {l1x,l1y,l2x,l2y}
  __half WQ2[25][25][8];        // 10000  {wlA,wsA,wlB,wsB} for t=2t2,2t2+1
  __half Wg[MULC][MULC];        // 5000
  float  W1[NBC][HIDC];         // 4000
  float  b1[104];               // 416
  __half W2i[50][152][2];       // 30400  [h/2][c][h&1], c=u*3+p
  __half pad[4];                // -> 79824 (16-mult)
};
static_assert(sizeof(PW) % 16 == 0, "PW must be 16B multiple");

__device__ PW PWg[3];

struct SM {
  float X[TE][MULC][12];
  float s[TE][MULC];
  float shv[TE][12];
  float emb[TE][12];
  PW pw;                        // offset 86272 (16-aligned)
};

__device__ __forceinline__ float geluf(float x) {
  float x3 = x * x * x;
  float t = tanhf(0.7978845608028654f * (x + 0.044715f * x3));
  return 0.5f * x * (1.0f + t);
}
__device__ __forceinline__ float sigmoidf(float x) { return 1.0f / (1.0f + expf(-x)); }
__device__ __forceinline__ float siluf(float x) { return x * sigmoidf(x); }

__device__ __forceinline__ float2 ldh2(const __half* p) {
  return __half22float2(*reinterpret_cast<const __half2*>(p));
}
__device__ __forceinline__ float2 h2f(unsigned v) {
  return __half22float2(*reinterpret_cast<const __half2*>(&v));
}
__device__ __forceinline__ u64 pk(float lo, float hi) {
  u64 r; asm("mov.b64 %0, {%1, %2};" : "=l"(r) : "f"(lo), "f"(hi)); return r;
}
__device__ __forceinline__ void upk(float& lo, float& hi, u64 v) {
  asm("mov.b64 {%0, %1}, %2;" : "=f"(lo), "=f"(hi) : "l"(v));
}
__device__ __forceinline__ void fma2(u64& d, u64 a, u64 b) {
  asm("fma.rn.f32x2 %0, %1, %2, %3;" : "=l"(d) : "l"(a), "l"(b), "l"(d));
}

// ---------------- pre-kernel: repack all weights once ----------------
__global__ void pack_kernel(const float* __restrict__ Wsc_g,
                            const float* __restrict__ Wlin1_g,
                            const float* __restrict__ Wlin2_g,
                            const float* __restrict__ Wgate_g,
                            const float* __restrict__ W1_g,
                            const float* __restrict__ b1_g,
                            const float* __restrict__ W2_g)
{
  const int i = blockIdx.x;            // layer
  PW* p = &PWg[i];
  const float* wsc = Wsc_g + i * 7500;
  const float* wl2 = Wlin2_g + i * 7500;
  const float* wl1 = Wlin1_g + i * 7500;   // l=0 block = first 2500

  // P0/P1/P2
  for (int t = threadIdx.x; t < 50 * 25; t += blockDim.x) {
    int u = t / 25;
    int v2 = t - u * 25;
    int c0 = 2 * v2, c1 = 2 * v2 + 1;
    __half* q0 = &p->P0[u][v2][0];
    q0[0] = __float2half_rn(wsc[0 * 2500 + u * 50 + c0]);
    q0[1] = __float2half_rn(wsc[0 * 2500 + u * 50 + c1]);
    q0[2] = __float2half_rn(wsc[1 * 2500 + u * 50 + c0]);
    q0[3] = __float2half_rn(wsc[1 * 2500 + u * 50 + c1]);
    __half* q1 = &p->P1[u][v2][0];
    q1[0] = __float2half_rn(wsc[2 * 2500 + u * 50 + c0]);
    q1[1] = __float2half_rn(wsc[2 * 2500 + u * 50 + c1]);
    q1[2] = __float2half_rn(wl2[0 * 2500 + u * 50 + c0]);
    q1[3] = __float2half_rn(wl2[0 * 2500 + u * 50 + c1]);
    __half* q2 = &p->P2[u][v2][0];
    q2[0] = __float2half_rn(wl2[1 * 2500 + u * 50 + c0]);
    q2[1] = __float2half_rn(wl2[1 * 2500 + u * 50 + c1]);
    q2[2] = __float2half_rn(wl2[2 * 2500 + u * 50 + c0]);
    q2[3] = __float2half_rn(wl2[2 * 2500 + u * 50 + c1]);
  }
  // WQ2
  for (int t = threadIdx.x; t < 25 * 25; t += blockDim.x) {
    int t2 = t / 25;
    int v2 = t - t2 * 25;
    int c0 = 2 * v2, c1 = 2 * v2 + 1;
    int ta = 2 * t2, tb = 2 * t2 + 1;
    __half* q = &p->WQ2[t2][v2][0];
    q[0] = __float2half_rn(wl1[ta * 50 + c0]);
    q[1] = __float2half_rn(wl1[ta * 50 + c1]);
    q[2] = __float2half_rn(wsc[ta * 50 + c0]);
    q[3] = __float2half_rn(wsc[ta * 50 + c1]);
    q[4] = __float2half_rn(wl1[tb * 50 + c0]);
    q[5] = __float2half_rn(wl1[tb * 50 + c1]);
    q[6] = __float2half_rn(wsc[tb * 50 + c0]);
    q[7] = __float2half_rn(wsc[tb * 50 + c1]);
  }
  // Wg
  {
    __half* d = &p->Wg[0][0];
    for (int t = threadIdx.x; t < 2500; t += blockDim.x)
      d[t] = __float2half_rn(Wgate_g[i * 2500 + t]);
  }
  // W1, b1
  {
    float* f = &p->W1[0][0];
    for (int t = threadIdx.x; t < 1000; t += blockDim.x) f[t] = W1_g[i * 1000 + t];
    for (int t = threadIdx.x; t < 104; t += blockDim.x)
      p->b1[t] = (t < 100) ? b1_g[i * 100 + t] : 0.0f;
  }
  // W2i
  {
    const float* g = W2_g + i * 75000;
    for (int t = threadIdx.x; t < 15000; t += blockDim.x) {
      int h = t / 150;
      int c = t - h * 150;
      int u = c / 3;
      int pp = c - u * 3;
      p->W2i[h >> 1][c][h & 1] = __float2half_rn(g[h * 750 + u * 15 + pp]);
    }
  }
}

// ---------------- main kernel ----------------
__global__ __launch_bounds__(NTHREADS, 1)
void slinky_kernel(const float* __restrict__ node_pos,
                   const float* __restrict__ bar_alpha,
                   const float* __restrict__ W_embed,
                   const float* __restrict__ Wout_g,
                   float* __restrict__ out)
{
  extern __shared__ __align__(16) float smem_raw[];
  SM* sm = reinterpret_cast<SM*>(smem_raw);

  const int tid = threadIdx.x;
  const int w   = tid >> 5;
  const int ln  = tid & 31;
  const int e0  = 2 * w;
  const int e1  = 2 * w + 1;
  const bool act = (ln < 25);
  const int u0 = 2 * ln;

  const float INVS50 = 0.1414213562373095f;
  const float CS = 0.9238795325112867f;
  const float CX = 0.3826834323650898f;
  const float CXK0 = CX * 0.05773502691896258f;
  const float CXK1 = CX * 0.02357022603955159f;
  const float CXK2 = CX * 0.01825741858350554f;

  // ---------------- preprocess ----------------
  {
    const int half = ln >> 4;
    const int l16 = ln & 15;
    const int le = e0 + half;
    const int eg = blockIdx.x * TE + le;
    const float* p6 = node_pos + (size_t)eg * 6;
    float ex = p6[1] - p6[0];
    float ey = p6[3] - p6[2];
    float ez = p6[5] - p6[4];
    float r = sqrtf(ex * ex + ey * ey + ez * ez);
    float inv = 1.0f / fmaxf(r, 1e-12f);
    float vx = ex * inv, vy = ey * inv, vz = ez * inv;
    if (l16 == 0) {
      const float s3 = 1.7320508075688772f;
      const float s5 = 2.23606797749979f;
      const float s15 = 3.872983346207417f;
      float* shp = sm->shv[le];
      shp[0] = 1.0f;
      shp[1] = s3 * vx;
      shp[2] = s3 * vy;
      shp[3] = s3 * vz;
      shp[4] = s15 * vx * vz;
      shp[5] = s15 * vx * vy;
      shp[6] = s5 * (vy * vy - 0.5f * (vx * vx + vz * vz));
      shp[7] = s15 * vy * vz;
      shp[8] = 0.5f * s15 * (vz * vz - vx * vx);
    }
    if (l16 < NBC) {
      const float step = 4.0f / 11.0f;
      float c = (float)(l16 + 1) * step;
      float diff = (r - c) / step;
      float up = diff + 1.0f, um = 1.0f - diff;
      float ua = (up > 0.0f) ? expf(-1.0f / up) : 0.0f;
      float ub = (um > 0.0f) ? expf(-1.0f / um) : 0.0f;
      sm->emb[le][l16] = (1.14136f * 7.3890560989306495f * 3.1622776601683795f) * ua * ub;
    }
    if (l16 >= NBC && l16 < 12) sm->emb[le][l16] = 0.0f;
  }
  if (act) {
    const int geb = blockIdx.x * TE;
    #pragma unroll
    for (int e = 0; e < 2; e++) {
      int le = e0 + e;
      int eg = geb + le;
      float ba_s = bar_alpha[2 * eg];
      float ba_d = bar_alpha[2 * eg + 1];
      #pragma unroll
      for (int ch = 0; ch < 2; ch++) {
        int u = u0 + ch;
        float we = W_embed[u];
        sm->s[le][u] = ba_s * we;
        float* xr = sm->X[le][u];
        xr[0] = 0.0f; xr[1] = 0.0f; xr[2] = 0.0f;
        xr[3] = ba_d * we;                        // x0 at phys 3
        xr[4] = 0.0f; xr[5] = 0.0f; xr[6] = 0.0f; xr[7] = 0.0f; xr[8] = 0.0f;
      }
    }
  }

  float xs[2][2][3];   // layer-2 l=1 values

  // ---------------- layers ----------------
  for (int i = 0; i < 3; i++) {
    __syncthreads();
    // weight staging: one contiguous vector copy
    {
      const uint4* src = reinterpret_cast<const uint4*>(&PWg[i]);
      uint4* dst = reinterpret_cast<uint4*>(&sm->pw);
      for (int t = tid; t < (int)(sizeof(PW) / 16); t += NTHREADS) dst[t] = src[t];
    }
    __syncthreads();

    // ---- stage 1a: radial MLP hidden -> X slots 10/11 (h pairs) ----
    #pragma unroll
    for (int j = 0; j < 4; j++) {
      int h = ln + 32 * j;
      if (h < HIDC) {
        float a0 = 0.0f, a1 = 0.0f;
        #pragma unroll
        for (int b2 = 0; b2 < 5; b2++) {
          float2 ea = *reinterpret_cast<const float2*>(&sm->emb[e0][2 * b2]);
          float2 eb = *reinterpret_cast<const float2*>(&sm->emb[e1][2 * b2]);
          float w1a = sm->pw.W1[2 * b2][h];
          float w1b = sm->pw.W1[2 * b2 + 1][h];
          a0 = fmaf(ea.x, w1a, a0); a0 = fmaf(ea.y, w1b, a0);
          a1 = fmaf(eb.x, w1a, a1); a1 = fmaf(eb.y, w1b, a1);
        }
        sm->X[e0][h >> 1][10 + (h & 1)] = geluf(a0 * 0.31622776601683794f + sm->pw.b1[h]);
        sm->X[e1][h >> 1][10 + (h & 1)] = geluf(a1 * 0.31622776601683794f + sm->pw.b1[h]);
      }
    }
    __syncwarp();

    // ---- stage 1b: pairwise-h matvec (f32x2 over h parity) ----
    u64 AC0[6] = {}, AC1[6] = {};
    if (act) {
      #pragma unroll 2
      for (int h2 = 0; h2 < 50; h2++) {
        u64 H0 = *reinterpret_cast<const u64*>(&sm->X[e0][h2][10]);
        u64 H1 = *reinterpret_cast<const u64*>(&sm->X[e1][h2][10]);
        const __half* wp = &sm->pw.W2i[h2][6 * ln][0];
        #pragma unroll
        for (int j = 0; j < 6; j++) {
          float2 wj = ldh2(wp + 2 * j);
          u64 W = pk(wj.x, wj.y);
          fma2(AC0[j], H0, W);
          fma2(AC1[j], H1, W);
        }
      }
    }
    float wv[2][2][3];
    #pragma unroll
    for (int j = 0; j < 6; j++) {
      float lo, hi;
      upk(lo, hi, AC0[j]); wv[0][j / 3][j % 3] = lo + hi;
      upk(lo, hi, AC1[j]); wv[1][j / 3][j % 3] = lo + hi;
    }

    // ---- stage 2: source matvecs (2 t per iter, 1 LDS.128 weights) ----
    u64 H0p = 0ull, H1p = 0ull, SC0p = 0ull, SC1p = 0ull;
    if (act) {
      #pragma unroll 5
      for (int t2 = 0; t2 < 25; t2++) {
        float2 sa = *reinterpret_cast<const float2*>(&sm->s[e0][2 * t2]);
        float2 sb = *reinterpret_cast<const float2*>(&sm->s[e1][2 * t2]);
        uint4 q = *reinterpret_cast<const uint4*>(&sm->pw.WQ2[t2][ln][0]);
        float2 wlA = h2f(q.x), wsA = h2f(q.y), wlB = h2f(q.z), wsB = h2f(q.w);
        u64 WLA = pk(wlA.x, wlA.y), WSA = pk(wsA.x, wsA.y);
        u64 WLB = pk(wlB.x, wlB.y), WSB = pk(wsB.x, wsB.y);
        u64 SA0 = pk(sa.x, sa.x), SB0 = pk(sb.x, sb.x);
        u64 SA1 = pk(sa.y, sa.y), SB1 = pk(sb.y, sb.y);
        fma2(H0p, SA0, WLA); fma2(SC0p, SA0, WSA);
        fma2(H1p, SB0, WLA); fma2(SC1p, SB0, WSA);
        fma2(H0p, SA1, WLB); fma2(SC0p, SA1, WSB);
        fma2(H1p, SB1, WLB); fma2(SC1p, SB1, WSB);
      }
    }
    float h0a[2][2], sca[2][2];
    upk(h0a[0][0], h0a[0][1], H0p);
    upk(h0a[1][0], h0a[1][1], H1p);
    upk(sca[0][0], sca[0][1], SC0p);
    upk(sca[1][0], sca[1][1], SC1p);
    __syncwarp();
    if (act) {
      #pragma unroll
      for (int e = 0; e < 2; e++) {
        int le = e0 + e;
        #pragma unroll
        for (int ch = 0; ch < 2; ch++) {
          int u = u0 + ch;
          float h0 = h0a[e][ch] * INVS50;
          float* xr = sm->X[le][u];
          xr[9]  = h0 * wv[e][ch][0] * 0.1f;   // a0
          xr[10] = h0 * wv[e][ch][1] * 0.1f;   // a1
          xr[11] = h0 * wv[e][ch][2] * 0.1f;   // a2
          sm->s[le][u] = siluf(CS * sca[e][ch] * INVS50);
        }
      }
    }
    __syncwarp();

    // ---- stage 3: packed f32x2; pairs (x1,x2)(x3,x0)(x4,x5)(x6,x7)(x8,a0)(a1,a2) ----
    u64 A[2][2][6] = {};
    if (act) {
      #pragma unroll 2
      for (int u = 0; u < MULC; u++) {
        uint2 p0 = *reinterpret_cast<const uint2*>(&sm->pw.P0[u][ln][0]);
        uint2 p1 = *reinterpret_cast<const uint2*>(&sm->pw.P1[u][ln][0]);
        uint2 p2 = *reinterpret_cast<const uint2*>(&sm->pw.P2[u][ln][0]);
        float2 ws0 = h2f(p0.x), ws1 = h2f(p0.y);
        float2 ws2 = h2f(p1.x), l0 = h2f(p1.y);
        float2 l1 = h2f(p2.x), l2 = h2f(p2.y);
        u64 Q0x = pk(ws1.x, ws1.x);
        u64 Q1x = pk(ws1.x, ws0.x);
        u64 Q2x = pk(ws2.x, ws2.x);
        u64 Q3x = pk(ws2.x, l0.x);
        u64 Q4x = pk(l1.x, l2.x);
        u64 Q0y = pk(ws1.y, ws1.y);
        u64 Q1y = pk(ws1.y, ws0.y);
        u64 Q2y = pk(ws2.y, ws2.y);
        u64 Q3y = pk(ws2.y, l0.y);
        u64 Q4y = pk(l1.y, l2.y);
        {
          const ulonglong2* xp = reinterpret_cast<const ulonglong2*>(sm->X[e0][u]);
          ulonglong2 xa = xp[0], xb = xp[1], xc = xp[2];
          fma2(A[0][0][0], xa.x, Q0x);
          fma2(A[0][0][1], xa.y, Q1x);
          fma2(A[0][0][2], xb.x, Q2x);
          fma2(A[0][0][3], xb.y, Q2x);
          fma2(A[0][0][4], xc.x, Q3x);
          fma2(A[0][0][5], xc.y, Q4x);
          fma2(A[0][1][0], xa.x, Q0y);
          fma2(A[0][1][1], xa.y, Q1y);
          fma2(A[0][1][2], xb.x, Q2y);
          fma2(A[0][1][3], xb.y, Q2y);
          fma2(A[0][1][4], xc.x, Q3y);
          fma2(A[0][1][5], xc.y, Q4y);
        }
        {
          const ulonglong2* xp = reinterpret_cast<const ulonglong2*>(sm->X[e1][u]);
          ulonglong2 xa = xp[0], xb = xp[1], xc = xp[2];
          fma2(A[1][0][0], xa.x, Q0x);
          fma2(A[1][0][1], xa.y, Q1x);
          fma2(A[1][0][2], xb.x, Q2x);
          fma2(A[1][0][3], xb.y, Q2x);
          fma2(A[1][0][4], xc.x, Q3x);
          fma2(A[1][0][5], xc.y, Q4x);
          fma2(A[1][1][0], xa.x, Q0y);
          fma2(A[1][1][1], xa.y, Q1y);
          fma2(A[1][1][2], xb.x, Q2y);
          fma2(A[1][1][3], xb.y, Q2y);
          fma2(A[1][1][4], xc.x, Q3y);
          fma2(A[1][1][5], xc.y, Q4y);
        }
      }
    }
    __syncwarp();   // all lanes done reading X
    if (act) {
      #pragma unroll
      for (int e = 0; e < 2; e++) {
        int le = e0 + e;
        const float* shl = sm->shv[le];
        #pragma unroll
        for (int ch = 0; ch < 2; ch++) {
          int u = u0 + ch;
          float ac0, ac1, ac2, ac3, ac4, ac5, ac6, ac7, ac8, b0, b1v, b2;
          upk(ac1, ac2, A[e][ch][0]);
          upk(ac3, ac0, A[e][ch][1]);
          upk(ac4, ac5, A[e][ch][2]);
          upk(ac6, ac7, A[e][ch][3]);
          upk(ac8, b0,  A[e][ch][4]);
          upk(b1v, b2,  A[e][ch][5]);
          float* xr = sm->X[le][u];
          float x0n = CS * INVS50 * ac0 + CXK0 * b0;
          float y1 = CS * INVS50 * ac1 + CXK1 * b1v * shl[1];
          float y2 = CS * INVS50 * ac2 + CXK1 * b1v * shl[2];
          float y3 = CS * INVS50 * ac3 + CXK1 * b1v * shl[3];
          xr[3] = x0n;
          if (i < 2) {
            xr[0] = y1;
            xr[1] = y2;
            xr[2] = y3;
            xr[4] = CS * INVS50 * ac4 + CXK2 * b2 * shl[4];
            xr[5] = CS * INVS50 * ac5 + CXK2 * b2 * shl[5];
            xr[6] = CS * INVS50 * ac6 + CXK2 * b2 * shl[6];
            xr[7] = CS * INVS50 * ac7 + CXK2 * b2 * shl[7];
            xr[8] = CS * INVS50 * ac8 + CXK2 * b2 * shl[8];
          } else {
            xs[e][ch][0] = y1;
            xs[e][ch][1] = y2;
            xs[e][ch][2] = y3;
          }
        }
      }
    }
    __syncwarp();

    // ---- stage 4: gate (packed over ch) ----
    u64 GA0 = 0ull, GA1 = 0ull;
    if (act) {
      #pragma unroll 5
      for (int u = 0; u < MULC; u++) {
        float t0 = sm->X[e0][u][3];   // x0 at phys 3
        float t1 = sm->X[e1][u][3];
        float2 wg = ldh2(&sm->pw.Wg[u][u0]);
        u64 WG = pk(wg.x, wg.y);
        u64 T0 = pk(t0, t0), T1 = pk(t1, t1);
        fma2(GA0, T0, WG);
        fma2(GA1, T1, WG);
      }
    }
    float ga[2][2];
    upk(ga[0][0], ga[0][1], GA0);
    upk(ga[1][0], ga[1][1], GA1);
    __syncwarp();
    if (act) {
      #pragma unroll
      for (int e = 0; e < 2; e++) {
        int le = e0 + e;
        #pragma unroll
        for (int ch = 0; ch < 2; ch++) {
          int u = u0 + ch;
          float g = sigmoidf(ga[e][ch] * INVS50);
          if (i < 2) {
            float* xr = sm->X[le][u];
            float4 Af = *reinterpret_cast<const float4*>(xr);
            float4 Bf = *reinterpret_cast<const float4*>(xr + 4);
            float x8 = xr[8];
            float4 qa = make_float4(Af.x * g, Af.y * g, Af.z * g, siluf(Af.w));
            float4 qb = make_float4(Bf.x * g, Bf.y * g, Bf.z * g, Bf.w * g);
            *reinterpret_cast<float4*>(xr)     = qa;
            *reinterpret_cast<float4*>(xr + 4) = qb;
            xr[8] = x8 * g;
          } else {
            xs[e][ch][0] *= g;
            xs[e][ch][1] *= g;
            xs[e][ch][2] *= g;
          }
        }
      }
    }
    __syncwarp();
  }

  // ---------------- output (from registers) ----------------
  {
    float p[2][3] = {};
    if (act) {
      float wo0 = Wout_g[u0];
      float wo1 = Wout_g[u0 + 1];
      #pragma unroll
      for (int e = 0; e < 2; e++) {
        p[e][0] = xs[e][0][0] * wo0 + xs[e][1][0] * wo1;
        p[e][1] = xs[e][0][1] * wo0 + xs[e][1][1] * wo1;
        p[e][2] = xs[e][0][2] * wo0 + xs[e][1][2] * wo1;
      }
    }
    #pragma unroll
    for (int off = 16; off; off >>= 1) {
      #pragma unroll
      for (int e = 0; e < 2; e++) {
        p[e][0] += __shfl_xor_sync(0xffffffffu, p[e][0], off);
        p[e][1] += __shfl_xor_sync(0xffffffffu, p[e][1], off);
        p[e][2] += __shfl_xor_sync(0xffffffffu, p[e][2], off);
      }
    }
    if (ln == 0) {
      int eg0 = blockIdx.x * TE + e0;
      float* od = out + (size_t)(2 * eg0) * 3;
      od[0] = 0.0f; od[1] = 0.0f; od[2] = 0.0f;
      od[3] = p[0][0] * INVS50;
      od[4] = p[0][1] * INVS50;
      od[5] = p[0][2] * INVS50;
      od[6] = 0.0f; od[7] = 0.0f; od[8] = 0.0f;
      od[9]  = p[1][0] * INVS50;
      od[10] = p[1][1] * INVS50;
      od[11] = p[1][2] * INVS50;
    }
  }
}

extern "C" void kernel_launch(void* const* d_in, const int* in_sizes, int n_in,
                              void* d_out, int out_size) {
  const float* node_pos = (const float*)d_in[0];
  const float* bar_alpha = (const float*)d_in[1];
  const float* W_embed  = (const float*)d_in[2];
  const float* Wsc      = (const float*)d_in[3];
  const float* Wlin1    = (const float*)d_in[4];
  const float* W1       = (const float*)d_in[5];
  const float* b1       = (const float*)d_in[6];
  const float* W2       = (const float*)d_in[7];
  const float* Wlin2    = (const float*)d_in[8];
  const float* Wgate    = (const float*)d_in[9];
  const float* W_out    = (const float*)d_in[10];
  float* out = (float*)d_out;

  pack_kernel<<<3, 256>>>(Wsc, Wlin1, Wlin2, Wgate, W1, b1, W2);

  int E = in_sizes[0] / 6;
  size_t smem = sizeof(SM);
  cudaFuncSetAttribute(slinky_kernel, cudaFuncAttributeMaxDynamicSharedMemorySize, (int)smem);
  slinky_kernel<<<E / TE, NTHREADS, smem>>>(node_pos, bar_alpha, W_embed, W_out, out);
}

// round 15
// speedup vs baseline: 1.2615x; 1.2270x over previous
#include <cuda_runtime.h>
#include <cuda_fp16.h>

// SlinkyForcePredictor — fused per-edge kernel, v14.
// Base = v13 (645.9us). Structural change: the radial MLP (stages 1a+1b,
// ~36% of per-warp instructions) is a pure function of scalar r ->
// precomputed table Tabg[3][2048][152] with linear interp (err ~5e-5).
// W1/b1/W2i leave SMEM weights (80KB->45KB) -> double-buffered staging
// (one block-wide sync per layer, copy overlapped with compute).
// Stages 2/3/4 byte-identical to v13.
// X phys layout: [x1,x2,x3,x0,x4,x5,x6,x7,x8,a0,a1,a2].

#define MULC 50
#define NBC 10
#define HIDC 100
#define TE 32
#define NTHREADS 512
#define TABN 2048
#define TPTS 128

typedef unsigned long long u64;

struct alignas(16) PW {         // packed per-layer weights, 45008B
  __half P0[50][25][4];         // {ws0x,ws0y,ws1x,ws1y} per (u, ch-pair)
  __half P1[50][25][4];         // {ws2x,ws2y,l0x,l0y}
  __half P2[50][25][4];         // {l1x,l1y,l2x,l2y}
  __half WQ2[25][25][8];        // {wlA,wsA,wlB,wsB} for t=2t2,2t2+1
  __half Wg[MULC][MULC];
  __half pad[4];
};
static_assert(sizeof(PW) % 16 == 0, "PW must be 16B multiple");

__device__ PW PWg[3];
__device__ __align__(16) float Tabg[3][TABN][152];   // row: c=u*3+p, 150 used

struct SM {
  float X[TE][MULC][12];        // 76800
  float s[TE][MULC];            // 6400
  float shv[TE][12];            // 1536
  float rfrac[TE];              // 128
  int   ridx[TE];               // 128
  PW pw[2];                     // 2 x 45008 @ offset 84992 (16-aligned)
};

__device__ __forceinline__ float geluf(float x) {
  float x3 = x * x * x;
  float t = tanhf(0.7978845608028654f * (x + 0.044715f * x3));
  return 0.5f * x * (1.0f + t);
}
__device__ __forceinline__ float sigmoidf(float x) { return 1.0f / (1.0f + expf(-x)); }
__device__ __forceinline__ float siluf(float x) { return x * sigmoidf(x); }

__device__ __forceinline__ float2 ldh2(const __half* p) {
  return __half22float2(*reinterpret_cast<const __half2*>(p));
}
__device__ __forceinline__ float2 h2f(unsigned v) {
  return __half22float2(*reinterpret_cast<const __half2*>(&v));
}
__device__ __forceinline__ u64 pk(float lo, float hi) {
  u64 r; asm("mov.b64 %0, {%1, %2};" : "=l"(r) : "f"(lo), "f"(hi)); return r;
}
__device__ __forceinline__ void upk(float& lo, float& hi, u64 v) {
  asm("mov.b64 {%0, %1}, %2;" : "=f"(lo), "=f"(hi) : "l"(v));
}
__device__ __forceinline__ void fma2(u64& d, u64 a, u64 b) {
  asm("fma.rn.f32x2 %0, %1, %2, %3;" : "=l"(d) : "l"(a), "l"(b), "l"(d));
}

__device__ __forceinline__ float embf(float r, int b) {
  const float step = 4.0f / 11.0f;
  float c = (float)(b + 1) * step;
  float diff = (r - c) / step;
  float up = diff + 1.0f, um = 1.0f - diff;
  float ua = (up > 0.0f) ? expf(-1.0f / up) : 0.0f;
  float ub = (um > 0.0f) ? expf(-1.0f / um) : 0.0f;
  return (1.14136f * 7.3890560989306495f * 3.1622776601683795f) * ua * ub;
}

// ---------------- pre-kernel 1: repack matvec weights ----------------
__global__ void pack_kernel(const float* __restrict__ Wsc_g,
                            const float* __restrict__ Wlin1_g,
                            const float* __restrict__ Wlin2_g,
                            const float* __restrict__ Wgate_g)
{
  const int i = blockIdx.x;
  PW* p = &PWg[i];
  const float* wsc = Wsc_g + i * 7500;
  const float* wl2 = Wlin2_g + i * 7500;
  const float* wl1 = Wlin1_g + i * 7500;
  for (int t = threadIdx.x; t < 50 * 25; t += blockDim.x) {
    int u = t / 25;
    int v2 = t - u * 25;
    int c0 = 2 * v2, c1 = 2 * v2 + 1;
    __half* q0 = &p->P0[u][v2][0];
    q0[0] = __float2half_rn(wsc[0 * 2500 + u * 50 + c0]);
    q0[1] = __float2half_rn(wsc[0 * 2500 + u * 50 + c1]);
    q0[2] = __float2half_rn(wsc[1 * 2500 + u * 50 + c0]);
    q0[3] = __float2half_rn(wsc[1 * 2500 + u * 50 + c1]);
    __half* q1 = &p->P1[u][v2][0];
    q1[0] = __float2half_rn(wsc[2 * 2500 + u * 50 + c0]);
    q1[1] = __float2half_rn(wsc[2 * 2500 + u * 50 + c1]);
    q1[2] = __float2half_rn(wl2[0 * 2500 + u * 50 + c0]);
    q1[3] = __float2half_rn(wl2[0 * 2500 + u * 50 + c1]);
    __half* q2 = &p->P2[u][v2][0];
    q2[0] = __float2half_rn(wl2[1 * 2500 + u * 50 + c0]);
    q2[1] = __float2half_rn(wl2[1 * 2500 + u * 50 + c1]);
    q2[2] = __float2half_rn(wl2[2 * 2500 + u * 50 + c0]);
    q2[3] = __float2half_rn(wl2[2 * 2500 + u * 50 + c1]);
  }
  for (int t = threadIdx.x; t < 25 * 25; t += blockDim.x) {
    int t2 = t / 25;
    int v2 = t - t2 * 25;
    int c0 = 2 * v2, c1 = 2 * v2 + 1;
    int ta = 2 * t2, tb = 2 * t2 + 1;
    __half* q = &p->WQ2[t2][v2][0];
    q[0] = __float2half_rn(wl1[ta * 50 + c0]);
    q[1] = __float2half_rn(wl1[ta * 50 + c1]);
    q[2] = __float2half_rn(wsc[ta * 50 + c0]);
    q[3] = __float2half_rn(wsc[ta * 50 + c1]);
    q[4] = __float2half_rn(wl1[tb * 50 + c0]);
    q[5] = __float2half_rn(wl1[tb * 50 + c1]);
    q[6] = __float2half_rn(wsc[tb * 50 + c0]);
    q[7] = __float2half_rn(wsc[tb * 50 + c1]);
  }
  {
    __half* d = &p->Wg[0][0];
    for (int t = threadIdx.x; t < 2500; t += blockDim.x)
      d[t] = __float2half_rn(Wgate_g[i * 2500 + t]);
  }
}

// ---------------- pre-kernel 2: radial table builder ----------------
// grid (TABN/TPTS, 3), block 256, dynamic smem
__global__ void table_kernel(const float* __restrict__ W1_g,
                             const float* __restrict__ b1_g,
                             const float* __restrict__ W2_g)
{
  extern __shared__ float ts[];
  float* w1_s  = ts;                      // 1000
  float* b1_s  = ts + 1000;               // 100
  float* w2_s  = ts + 1104;               // 100*152 = 15200
  float* emb_s = ts + 16304;              // TPTS*10
  float* hid_s = ts + 16304 + TPTS * 10;  // TPTS*100

  const int i = blockIdx.y;
  const int p0 = blockIdx.x * TPTS;
  const int t = threadIdx.x;
  const float D = 4.0f / (float)(TABN - 1);

  for (int k = t; k < 1000; k += 256) w1_s[k] = W1_g[i * 1000 + k];
  for (int k = t; k < 100; k += 256) b1_s[k] = b1_g[i * 100 + k];
  for (int k = t; k < 15000; k += 256) {
    int h = k / 150, c = k - h * 150;
    int u = c / 3, pp = c - u * 3;
    w2_s[h * 152 + c] = W2_g[i * 75000 + h * 750 + u * 15 + pp];
  }
  for (int k = t; k < TPTS * 10; k += 256) {
    int p = k / 10, b = k - p * 10;
    emb_s[k] = embf((float)(p0 + p) * D, b);
  }
  __syncthreads();
  for (int k = t; k < TPTS * 100; k += 256) {
    int p = k / 100, h = k - p * 100;
    float a = 0.0f;
    #pragma unroll
    for (int b = 0; b < 10; b++) a = fmaf(emb_s[p * 10 + b], w1_s[b * 100 + h], a);
    hid_s[k] = geluf(a * 0.31622776601683794f + b1_s[h]);
  }
  __syncthreads();
  {
    int p = t >> 1;
    int c0 = (t & 1) * 75;
    float acc[75];
    #pragma unroll
    for (int j = 0; j < 75; j++) acc[j] = 0.0f;
    for (int h = 0; h < 100; h++) {
      float hv = hid_s[p * 100 + h];
      #pragma unroll
      for (int j = 0; j < 75; j++) acc[j] = fmaf(hv, w2_s[h * 152 + c0 + j], acc[j]);
    }
    float* row = &Tabg[i][p0 + p][0];
    for (int j = 0; j < 75; j++) row[c0 + j] = acc[j];
    if (t & 1) { row[150] = 0.0f; row[151] = 0.0f; }
  }
}

// ---------------- main kernel ----------------
__global__ __launch_bounds__(NTHREADS, 1)
void slinky_kernel(const float* __restrict__ node_pos,
                   const float* __restrict__ bar_alpha,
                   const float* __restrict__ W_embed,
                   const float* __restrict__ Wout_g,
                   float* __restrict__ out)
{
  extern __shared__ __align__(16) float smem_raw[];
  SM* sm = reinterpret_cast<SM*>(smem_raw);

  const int tid = threadIdx.x;
  const int w   = tid >> 5;
  const int ln  = tid & 31;
  const int e0  = 2 * w;
  const int e1  = 2 * w + 1;
  const bool act = (ln < 25);
  const int u0 = 2 * ln;

  const float INVS50 = 0.1414213562373095f;
  const float CS = 0.9238795325112867f;
  const float CX = 0.3826834323650898f;
  const float CXK0 = CX * 0.05773502691896258f;
  const float CXK1 = CX * 0.02357022603955159f;
  const float CXK2 = CX * 0.01825741858350554f;

  // ---------------- initial weight staging (layer 0) ----------------
  {
    const uint4* src = reinterpret_cast<const uint4*>(&PWg[0]);
    uint4* dst = reinterpret_cast<uint4*>(&sm->pw[0]);
    for (int t = tid; t < (int)(sizeof(PW) / 16); t += NTHREADS) dst[t] = src[t];
  }

  // ---------------- preprocess ----------------
  {
    const int half = ln >> 4;
    const int l16 = ln & 15;
    const int le = e0 + half;
    const int eg = blockIdx.x * TE + le;
    const float* p6 = node_pos + (size_t)eg * 6;
    float ex = p6[1] - p6[0];
    float ey = p6[3] - p6[2];
    float ez = p6[5] - p6[4];
    float r = sqrtf(ex * ex + ey * ey + ez * ez);
    float inv = 1.0f / fmaxf(r, 1e-12f);
    float vx = ex * inv, vy = ey * inv, vz = ez * inv;
    if (l16 == 0) {
      const float s3 = 1.7320508075688772f;
      const float s5 = 2.23606797749979f;
      const float s15 = 3.872983346207417f;
      float* shp = sm->shv[le];
      shp[0] = 1.0f;
      shp[1] = s3 * vx;
      shp[2] = s3 * vy;
      shp[3] = s3 * vz;
      shp[4] = s15 * vx * vz;
      shp[5] = s15 * vx * vy;
      shp[6] = s5 * (vy * vy - 0.5f * (vx * vx + vz * vz));
      shp[7] = s15 * vy * vz;
      shp[8] = 0.5f * s15 * (vz * vz - vx * vx);
      // table index + fraction (clamped; r>=4 -> last row = wv(4) exactly)
      const float invD = (float)(TABN - 1) / 4.0f;
      float q = r * invD;
      int idx = (int)q;
      if (idx > TABN - 2) idx = TABN - 2;
      float f = q - (float)idx;
      f = fminf(f, 1.0f);
      sm->ridx[le] = idx;
      sm->rfrac[le] = f;
    }
  }
  if (act) {
    const int geb = blockIdx.x * TE;
    #pragma unroll
    for (int e = 0; e < 2; e++) {
      int le = e0 + e;
      int eg = geb + le;
      float ba_s = bar_alpha[2 * eg];
      float ba_d = bar_alpha[2 * eg + 1];
      #pragma unroll
      for (int ch = 0; ch < 2; ch++) {
        int u = u0 + ch;
        float we = W_embed[u];
        sm->s[le][u] = ba_s * we;
        float* xr = sm->X[le][u];
        xr[0] = 0.0f; xr[1] = 0.0f; xr[2] = 0.0f;
        xr[3] = ba_d * we;                        // x0 at phys 3
        xr[4] = 0.0f; xr[5] = 0.0f; xr[6] = 0.0f; xr[7] = 0.0f; xr[8] = 0.0f;
      }
    }
  }
  __syncthreads();

  float xs[2][2][3];   // layer-2 l=1 values

  // ---------------- layers ----------------
  for (int i = 0; i < 3; i++) {
    const PW* cw = &sm->pw[i & 1];
    // prefetch next layer's weights into the other buffer (no sync needed now)
    if (i < 2) {
      const uint4* src = reinterpret_cast<const uint4*>(&PWg[i + 1]);
      uint4* dst = reinterpret_cast<uint4*>(&sm->pw[(i + 1) & 1]);
      for (int t = tid; t < (int)(sizeof(PW) / 16); t += NTHREADS) dst[t] = src[t];
    }

    // ---- wv from radial table (replaces stages 1a/1b) ----
    float wv[2][2][3];
    if (act) {
      #pragma unroll
      for (int e = 0; e < 2; e++) {
        int le = e0 + e;
        int idx = sm->ridx[le];
        float f = sm->rfrac[le];
        const float* r0 = &Tabg[i][idx][6 * ln];
        const float* r1 = r0 + 152;
        float2 a0 = *reinterpret_cast<const float2*>(r0);
        float2 a1 = *reinterpret_cast<const float2*>(r0 + 2);
        float2 a2 = *reinterpret_cast<const float2*>(r0 + 4);
        float2 b0 = *reinterpret_cast<const float2*>(r1);
        float2 b1v = *reinterpret_cast<const float2*>(r1 + 2);
        float2 b2 = *reinterpret_cast<const float2*>(r1 + 4);
        wv[e][0][0] = a0.x + f * (b0.x - a0.x);
        wv[e][0][1] = a0.y + f * (b0.y - a0.y);
        wv[e][0][2] = a1.x + f * (b1v.x - a1.x);
        wv[e][1][0] = a1.y + f * (b1v.y - a1.y);
        wv[e][1][1] = a2.x + f * (b2.x - a2.x);
        wv[e][1][2] = a2.y + f * (b2.y - a2.y);
      }
    }

    // ---- stage 2: source matvecs (2 t per iter, 1 LDS.128 weights) ----
    u64 H0p = 0ull, H1p = 0ull, SC0p = 0ull, SC1p = 0ull;
    if (act) {
      #pragma unroll 5
      for (int t2 = 0; t2 < 25; t2++) {
        float2 sa = *reinterpret_cast<const float2*>(&sm->s[e0][2 * t2]);
        float2 sb = *reinterpret_cast<const float2*>(&sm->s[e1][2 * t2]);
        uint4 q = *reinterpret_cast<const uint4*>(&cw->WQ2[t2][ln][0]);
        float2 wlA = h2f(q.x), wsA = h2f(q.y), wlB = h2f(q.z), wsB = h2f(q.w);
        u64 WLA = pk(wlA.x, wlA.y), WSA = pk(wsA.x, wsA.y);
        u64 WLB = pk(wlB.x, wlB.y), WSB = pk(wsB.x, wsB.y);
        u64 SA0 = pk(sa.x, sa.x), SB0 = pk(sb.x, sb.x);
        u64 SA1 = pk(sa.y, sa.y), SB1 = pk(sb.y, sb.y);
        fma2(H0p, SA0, WLA); fma2(SC0p, SA0, WSA);
        fma2(H1p, SB0, WLA); fma2(SC1p, SB0, WSA);
        fma2(H0p, SA1, WLB); fma2(SC0p, SA1, WSB);
        fma2(H1p, SB1, WLB); fma2(SC1p, SB1, WSB);
      }
    }
    float h0a[2][2], sca[2][2];
    upk(h0a[0][0], h0a[0][1], H0p);
    upk(h0a[1][0], h0a[1][1], H1p);
    upk(sca[0][0], sca[0][1], SC0p);
    upk(sca[1][0], sca[1][1], SC1p);
    __syncwarp();
    if (act) {
      #pragma unroll
      for (int e = 0; e < 2; e++) {
        int le = e0 + e;
        #pragma unroll
        for (int ch = 0; ch < 2; ch++) {
          int u = u0 + ch;
          float h0 = h0a[e][ch] * INVS50;
          float* xr = sm->X[le][u];
          xr[9]  = h0 * wv[e][ch][0] * 0.1f;   // a0
          xr[10] = h0 * wv[e][ch][1] * 0.1f;   // a1
          xr[11] = h0 * wv[e][ch][2] * 0.1f;   // a2
          sm->s[le][u] = siluf(CS * sca[e][ch] * INVS50);
        }
      }
    }
    __syncwarp();

    // ---- stage 3: packed f32x2; pairs (x1,x2)(x3,x0)(x4,x5)(x6,x7)(x8,a0)(a1,a2) ----
    u64 A[2][2][6] = {};
    if (act) {
      #pragma unroll 2
      for (int u = 0; u < MULC; u++) {
        uint2 p0 = *reinterpret_cast<const uint2*>(&cw->P0[u][ln][0]);
        uint2 p1 = *reinterpret_cast<const uint2*>(&cw->P1[u][ln][0]);
        uint2 p2 = *reinterpret_cast<const uint2*>(&cw->P2[u][ln][0]);
        float2 ws0 = h2f(p0.x), ws1 = h2f(p0.y);
        float2 ws2 = h2f(p1.x), l0 = h2f(p1.y);
        float2 l1 = h2f(p2.x), l2 = h2f(p2.y);
        u64 Q0x = pk(ws1.x, ws1.x);
        u64 Q1x = pk(ws1.x, ws0.x);
        u64 Q2x = pk(ws2.x, ws2.x);
        u64 Q3x = pk(ws2.x, l0.x);
        u64 Q4x = pk(l1.x, l2.x);
        u64 Q0y = pk(ws1.y, ws1.y);
        u64 Q1y = pk(ws1.y, ws0.y);
        u64 Q2y = pk(ws2.y, ws2.y);
        u64 Q3y = pk(ws2.y, l0.y);
        u64 Q4y = pk(l1.y, l2.y);
        {
          const ulonglong2* xp = reinterpret_cast<const ulonglong2*>(sm->X[e0][u]);
          ulonglong2 xa = xp[0], xb = xp[1], xc = xp[2];
          fma2(A[0][0][0], xa.x, Q0x);
          fma2(A[0][0][1], xa.y, Q1x);
          fma2(A[0][0][2], xb.x, Q2x);
          fma2(A[0][0][3], xb.y, Q2x);
          fma2(A[0][0][4], xc.x, Q3x);
          fma2(A[0][0][5], xc.y, Q4x);
          fma2(A[0][1][0], xa.x, Q0y);
          fma2(A[0][1][1], xa.y, Q1y);
          fma2(A[0][1][2], xb.x, Q2y);
          fma2(A[0][1][3], xb.y, Q2y);
          fma2(A[0][1][4], xc.x, Q3y);
          fma2(A[0][1][5], xc.y, Q4y);
        }
        {
          const ulonglong2* xp = reinterpret_cast<const ulonglong2*>(sm->X[e1][u]);
          ulonglong2 xa = xp[0], xb = xp[1], xc = xp[2];
          fma2(A[1][0][0], xa.x, Q0x);
          fma2(A[1][0][1], xa.y, Q1x);
          fma2(A[1][0][2], xb.x, Q2x);
          fma2(A[1][0][3], xb.y, Q2x);
          fma2(A[1][0][4], xc.x, Q3x);
          fma2(A[1][0][5], xc.y, Q4x);
          fma2(A[1][1][0], xa.x, Q0y);
          fma2(A[1][1][1], xa.y, Q1y);
          fma2(A[1][1][2], xb.x, Q2y);
          fma2(A[1][1][3], xb.y, Q2y);
          fma2(A[1][1][4], xc.x, Q3y);
          fma2(A[1][1][5], xc.y, Q4y);
        }
      }
    }
    __syncwarp();   // all lanes done reading X
    if (act) {
      #pragma unroll
      for (int e = 0; e < 2; e++) {
        int le = e0 + e;
        const float* shl = sm->shv[le];
        #pragma unroll
        for (int ch = 0; ch < 2; ch++) {
          int u = u0 + ch;
          float ac0, ac1, ac2, ac3, ac4, ac5, ac6, ac7, ac8, b0, b1v, b2;
          upk(ac1, ac2, A[e][ch][0]);
          upk(ac3, ac0, A[e][ch][1]);
          upk(ac4, ac5, A[e][ch][2]);
          upk(ac6, ac7, A[e][ch][3]);
          upk(ac8, b0,  A[e][ch][4]);
          upk(b1v, b2,  A[e][ch][5]);
          float* xr = sm->X[le][u];
          float x0n = CS * INVS50 * ac0 + CXK0 * b0;
          float y1 = CS * INVS50 * ac1 + CXK1 * b1v * shl[1];
          float y2 = CS * INVS50 * ac2 + CXK1 * b1v * shl[2];
          float y3 = CS * INVS50 * ac3 + CXK1 * b1v * shl[3];
          xr[3] = x0n;
          if (i < 2) {
            xr[0] = y1;
            xr[1] = y2;
            xr[2] = y3;
            xr[4] = CS * INVS50 * ac4 + CXK2 * b2 * shl[4];
            xr[5] = CS * INVS50 * ac5 + CXK2 * b2 * shl[5];
            xr[6] = CS * INVS50 * ac6 + CXK2 * b2 * shl[6];
            xr[7] = CS * INVS50 * ac7 + CXK2 * b2 * shl[7];
            xr[8] = CS * INVS50 * ac8 + CXK2 * b2 * shl[8];
          } else {
            xs[e][ch][0] = y1;
            xs[e][ch][1] = y2;
            xs[e][ch][2] = y3;
          }
        }
      }
    }
    __syncwarp();

    // ---- stage 4: gate (packed over ch) ----
    u64 GA0 = 0ull, GA1 = 0ull;
    if (act) {
      #pragma unroll 5
      for (int u = 0; u < MULC; u++) {
        float t0 = sm->X[e0][u][3];   // x0 at phys 3
        float t1 = sm->X[e1][u][3];
        float2 wg = ldh2(&cw->Wg[u][u0]);
        u64 WG = pk(wg.x, wg.y);
        u64 T0 = pk(t0, t0), T1 = pk(t1, t1);
        fma2(GA0, T0, WG);
        fma2(GA1, T1, WG);
      }
    }
    float ga[2][2];
    upk(ga[0][0], ga[0][1], GA0);
    upk(ga[1][0], ga[1][1], GA1);
    __syncwarp();
    if (act) {
      #pragma unroll
      for (int e = 0; e < 2; e++) {
        int le = e0 + e;
        #pragma unroll
        for (int ch = 0; ch < 2; ch++) {
          int u = u0 + ch;
          float g = sigmoidf(ga[e][ch] * INVS50);
          if (i < 2) {
            float* xr = sm->X[le][u];
            float4 Af = *reinterpret_cast<const float4*>(xr);
            float4 Bf = *reinterpret_cast<const float4*>(xr + 4);
            float x8 = xr[8];
            float4 qa = make_float4(Af.x * g, Af.y * g, Af.z * g, siluf(Af.w));
            float4 qb = make_float4(Bf.x * g, Bf.y * g, Bf.z * g, Bf.w * g);
            *reinterpret_cast<float4*>(xr)     = qa;
            *reinterpret_cast<float4*>(xr + 4) = qb;
            xr[8] = x8 * g;
          } else {
            xs[e][ch][0] *= g;
            xs[e][ch][1] *= g;
            xs[e][ch][2] *= g;
          }
        }
      }
    }
    __syncthreads();   // pw[i&1] reads done; pw[(i+1)&1] copy complete
  }

  // ---------------- output (from registers) ----------------
  {
    float p[2][3] = {};
    if (act) {
      float wo0 = Wout_g[u0];
      float wo1 = Wout_g[u0 + 1];
      #pragma unroll
      for (int e = 0; e < 2; e++) {
        p[e][0] = xs[e][0][0] * wo0 + xs[e][1][0] * wo1;
        p[e][1] = xs[e][0][1] * wo0 + xs[e][1][1] * wo1;
        p[e][2] = xs[e][0][2] * wo0 + xs[e][1][2] * wo1;
      }
    }
    #pragma unroll
    for (int off = 16; off; off >>= 1) {
      #pragma unroll
      for (int e = 0; e < 2; e++) {
        p[e][0] += __shfl_xor_sync(0xffffffffu, p[e][0], off);
        p[e][1] += __shfl_xor_sync(0xffffffffu, p[e][1], off);
        p[e][2] += __shfl_xor_sync(0xffffffffu, p[e][2], off);
      }
    }
    if (ln == 0) {
      int eg0 = blockIdx.x * TE + e0;
      float* od = out + (size_t)(2 * eg0) * 3;
      od[0] = 0.0f; od[1] = 0.0f; od[2] = 0.0f;
      od[3] = p[0][0] * INVS50;
      od[4] = p[0][1] * INVS50;
      od[5] = p[0][2] * INVS50;
      od[6] = 0.0f; od[7] = 0.0f; od[8] = 0.0f;
      od[9]  = p[1][0] * INVS50;
      od[10] = p[1][1] * INVS50;
      od[11] = p[1][2] * INVS50;
    }
  }
}

extern "C" void kernel_launch(void* const* d_in, const int* in_sizes, int n_in,
                              void* d_out, int out_size) {
  const float* node_pos = (const float*)d_in[0];
  const float* bar_alpha = (const float*)d_in[1];
  const float* W_embed  = (const float*)d_in[2];
  const float* Wsc      = (const float*)d_in[3];
  const float* Wlin1    = (const float*)d_in[4];
  const float* W1       = (const float*)d_in[5];
  const float* b1       = (const float*)d_in[6];
  const float* W2       = (const float*)d_in[7];
  const float* Wlin2    = (const float*)d_in[8];
  const float* Wgate    = (const float*)d_in[9];
  const float* W_out    = (const float*)d_in[10];
  float* out = (float*)d_out;

  pack_kernel<<<3, 256>>>(Wsc, Wlin1, Wlin2, Wgate);

  size_t tsmem = (size_t)(1104 + 15200 + TPTS * 10 + TPTS * 100) * 4;
  cudaFuncSetAttribute(table_kernel, cudaFuncAttributeMaxDynamicSharedMemorySize, (int)tsmem);
  table_kernel<<<dim3(TABN / TPTS, 3), 256, tsmem>>>(W1, b1, W2);

  int E = in_sizes[0] / 6;
  size_t smem = sizeof(SM);
  cudaFuncSetAttribute(slinky_kernel, cudaFuncAttributeMaxDynamicSharedMemorySize, (int)smem);
  slinky_kernel<<<E / TE, NTHREADS, smem>>>(node_pos, bar_alpha, W_embed, W_out, out);
}

// round 16
// speedup vs baseline: 1.3248x; 1.0502x over previous
#include <cuda_runtime.h>
#include <cuda_fp16.h>

// SlinkyForcePredictor — fused per-edge kernel, v15.
// Base = v14 (526.4us). New structural cut: the SOURCE-NODE chain
// (s_i, h0_i) is a pure 1-D function of ba_s -> tabulated like the radial MLP.
// Stage 2 (matvec x3 layers), s[] smem, and WQ2 weights are gone.
// pack_kernel parallelized (3 -> 12 blocks). Stages 3/4 identical to v14.
// X phys layout: [x1,x2,x3,x0,x4,x5,x6,x7,x8,a0,a1,a2].

#define MULC 50
#define NBC 10
#define HIDC 100
#define TE 32
#define NTHREADS 512
#define TABN 2048
#define TPTS 128
#define BAN 4096

typedef unsigned long long u64;

struct alignas(16) PW {         // packed per-layer weights, 35008B
  __half P0[50][25][4];         // {ws0x,ws0y,ws1x,ws1y} per (u, ch-pair)
  __half P1[50][25][4];         // {ws2x,ws2y,l0x,l0y}
  __half P2[50][25][4];         // {l1x,l1y,l2x,l2y}
  __half Wg[MULC][MULC];
  __half pad[4];
};
static_assert(sizeof(PW) % 16 == 0, "PW must be 16B multiple");

__device__ PW PWg[3];
__device__ __align__(16) float Tabg[3][TABN][152];    // radial: c=u*3+p
__device__ __align__(16) float H0Tabg[3][BAN][52];    // source: h0*INVS50*0.1

struct SM {
  float X[TE][MULC][12];        // 76800
  float shv[TE][12];            // 1536
  float rfrac[TE];              // 128
  int   ridx[TE];               // 128
  float bfrac[TE];              // 128
  int   bidx[TE];               // 128
  PW pw[2];                     // 70016 @ 78848 (16-aligned)
};

__device__ __forceinline__ float geluf(float x) {
  float x3 = x * x * x;
  float t = tanhf(0.7978845608028654f * (x + 0.044715f * x3));
  return 0.5f * x * (1.0f + t);
}
__device__ __forceinline__ float sigmoidf(float x) { return 1.0f / (1.0f + expf(-x)); }
__device__ __forceinline__ float siluf(float x) { return x * sigmoidf(x); }

__device__ __forceinline__ float2 ldh2(const __half* p) {
  return __half22float2(*reinterpret_cast<const __half2*>(p));
}
__device__ __forceinline__ float2 h2f(unsigned v) {
  return __half22float2(*reinterpret_cast<const __half2*>(&v));
}
__device__ __forceinline__ u64 pk(float lo, float hi) {
  u64 r; asm("mov.b64 %0, {%1, %2};" : "=l"(r) : "f"(lo), "f"(hi)); return r;
}
__device__ __forceinline__ void upk(float& lo, float& hi, u64 v) {
  asm("mov.b64 {%0, %1}, %2;" : "=f"(lo), "=f"(hi) : "l"(v));
}
__device__ __forceinline__ void fma2(u64& d, u64 a, u64 b) {
  asm("fma.rn.f32x2 %0, %1, %2, %3;" : "=l"(d) : "l"(a), "l"(b), "l"(d));
}

__device__ __forceinline__ float embf(float r, int b) {
  const float step = 4.0f / 11.0f;
  float c = (float)(b + 1) * step;
  float diff = (r - c) / step;
  float up = diff + 1.0f, um = 1.0f - diff;
  float ua = (up > 0.0f) ? expf(-1.0f / up) : 0.0f;
  float ub = (um > 0.0f) ? expf(-1.0f / um) : 0.0f;
  return (1.14136f * 7.3890560989306495f * 3.1622776601683795f) * ua * ub;
}

// ---------------- pre-kernel 1: repack matvec weights (12 blocks) ----------------
__global__ void pack_kernel(const float* __restrict__ Wsc_g,
                            const float* __restrict__ Wlin2_g,
                            const float* __restrict__ Wgate_g)
{
  const int i = blockIdx.x;
  const int off = blockIdx.y * blockDim.x + threadIdx.x;
  const int stride = blockDim.x * gridDim.y;
  PW* p = &PWg[i];
  const float* wsc = Wsc_g + i * 7500;
  const float* wl2 = Wlin2_g + i * 7500;
  for (int t = off; t < 50 * 25; t += stride) {
    int u = t / 25;
    int v2 = t - u * 25;
    int c0 = 2 * v2, c1 = 2 * v2 + 1;
    __half* q0 = &p->P0[u][v2][0];
    q0[0] = __float2half_rn(wsc[0 * 2500 + u * 50 + c0]);
    q0[1] = __float2half_rn(wsc[0 * 2500 + u * 50 + c1]);
    q0[2] = __float2half_rn(wsc[1 * 2500 + u * 50 + c0]);
    q0[3] = __float2half_rn(wsc[1 * 2500 + u * 50 + c1]);
    __half* q1 = &p->P1[u][v2][0];
    q1[0] = __float2half_rn(wsc[2 * 2500 + u * 50 + c0]);
    q1[1] = __float2half_rn(wsc[2 * 2500 + u * 50 + c1]);
    q1[2] = __float2half_rn(wl2[0 * 2500 + u * 50 + c0]);
    q1[3] = __float2half_rn(wl2[0 * 2500 + u * 50 + c1]);
    __half* q2 = &p->P2[u][v2][0];
    q2[0] = __float2half_rn(wl2[1 * 2500 + u * 50 + c0]);
    q2[1] = __float2half_rn(wl2[1 * 2500 + u * 50 + c1]);
    q2[2] = __float2half_rn(wl2[2 * 2500 + u * 50 + c0]);
    q2[3] = __float2half_rn(wl2[2 * 2500 + u * 50 + c1]);
  }
  for (int t = off; t < 2500; t += stride)
    (&p->Wg[0][0])[t] = __float2half_rn(Wgate_g[i * 2500 + t]);
}

// ---------------- pre-kernel 2: radial table builder ----------------
__global__ void table_kernel(const float* __restrict__ W1_g,
                             const float* __restrict__ b1_g,
                             const float* __restrict__ W2_g)
{
  extern __shared__ float ts[];
  float* w1_s  = ts;                      // 1000
  float* b1_s  = ts + 1000;               // 100
  float* w2_s  = ts + 1104;               // 15200
  float* emb_s = ts + 16304;              // TPTS*10
  float* hid_s = ts + 16304 + TPTS * 10;  // TPTS*100

  const int i = blockIdx.y;
  const int p0 = blockIdx.x * TPTS;
  const int t = threadIdx.x;
  const float D = 4.0f / (float)(TABN - 1);

  for (int k = t; k < 1000; k += 256) w1_s[k] = W1_g[i * 1000 + k];
  for (int k = t; k < 100; k += 256) b1_s[k] = b1_g[i * 100 + k];
  for (int k = t; k < 15000; k += 256) {
    int h = k / 150, c = k - h * 150;
    int u = c / 3, pp = c - u * 3;
    w2_s[h * 152 + c] = W2_g[i * 75000 + h * 750 + u * 15 + pp];
  }
  for (int k = t; k < TPTS * 10; k += 256) {
    int p = k / 10, b = k - p * 10;
    emb_s[k] = embf((float)(p0 + p) * D, b);
  }
  __syncthreads();
  for (int k = t; k < TPTS * 100; k += 256) {
    int p = k / 100, h = k - p * 100;
    float a = 0.0f;
    #pragma unroll
    for (int b = 0; b < 10; b++) a = fmaf(emb_s[p * 10 + b], w1_s[b * 100 + h], a);
    hid_s[k] = geluf(a * 0.31622776601683794f + b1_s[h]);
  }
  __syncthreads();
  {
    int p = t >> 1;
    int c0 = (t & 1) * 75;
    float acc[75];
    #pragma unroll
    for (int j = 0; j < 75; j++) acc[j] = 0.0f;
    for (int h = 0; h < 100; h++) {
      float hv = hid_s[p * 100 + h];
      #pragma unroll
      for (int j = 0; j < 75; j++) acc[j] = fmaf(hv, w2_s[h * 152 + c0 + j], acc[j]);
    }
    float* row = &Tabg[i][p0 + p][0];
    for (int j = 0; j < 75; j++) row[c0 + j] = acc[j];
    if (t & 1) { row[150] = 0.0f; row[151] = 0.0f; }
  }
}

// ---------------- pre-kernel 3: source-chain table builder ----------------
// 128 blocks x 256 thr; 32 points/block, 8 threads per point.
__global__ void h0tab_kernel(const float* __restrict__ Wsc_g,
                             const float* __restrict__ Wlin1_g,
                             const float* __restrict__ W_embed)
{
  __shared__ float s_cur[32][52];
  __shared__ float s_nxt[32][52];
  __shared__ float wl1_s[2500];
  __shared__ float wsc_s[2500];

  const int pl = threadIdx.x >> 3;     // local point 0..31
  const int vt = threadIdx.x & 7;
  const int p = blockIdx.x * 32 + pl;
  const float ba = -6.0f + 12.0f * (float)p / (float)(BAN - 1);
  const float KS = 0.9238795325112867f * 0.1414213562373095f;   // cs/sqrt(50)
  const float KH = 0.1414213562373095f * 0.1f;                  // 1/sqrt(50) * 0.1

  for (int v = vt; v < 50; v += 8) s_cur[pl][v] = ba * W_embed[v];
  __syncthreads();
  for (int i = 0; i < 3; i++) {
    for (int k = threadIdx.x; k < 2500; k += 256) {
      wl1_s[k] = Wlin1_g[i * 7500 + k];
      wsc_s[k] = Wsc_g[i * 7500 + k];
    }
    __syncthreads();
    for (int v = vt; v < 50; v += 8) {
      float h = 0.0f, sc = 0.0f;
      #pragma unroll 10
      for (int t = 0; t < 50; t++) {
        float sv = s_cur[pl][t];
        h  = fmaf(sv, wl1_s[t * 50 + v], h);
        sc = fmaf(sv, wsc_s[t * 50 + v], sc);
      }
      H0Tabg[i][p][v] = KH * h;
      s_nxt[pl][v] = siluf(KS * sc);
    }
    __syncthreads();
    for (int v = vt; v < 50; v += 8) s_cur[pl][v] = s_nxt[pl][v];
    __syncthreads();
  }
  if (vt == 0) { H0Tabg[0][p][50] = 0.0f; H0Tabg[0][p][51] = 0.0f; }
}

// ---------------- main kernel ----------------
__global__ __launch_bounds__(NTHREADS, 1)
void slinky_kernel(const float* __restrict__ node_pos,
                   const float* __restrict__ bar_alpha,
                   const float* __restrict__ W_embed,
                   const float* __restrict__ Wout_g,
                   float* __restrict__ out)
{
  extern __shared__ __align__(16) float smem_raw[];
  SM* sm = reinterpret_cast<SM*>(smem_raw);

  const int tid = threadIdx.x;
  const int w   = tid >> 5;
  const int ln  = tid & 31;
  const int e0  = 2 * w;
  const int e1  = 2 * w + 1;
  const bool act = (ln < 25);
  const int u0 = 2 * ln;

  const float INVS50 = 0.1414213562373095f;
  const float CS = 0.9238795325112867f;
  const float CX = 0.3826834323650898f;
  const float CXK0 = CX * 0.05773502691896258f;
  const float CXK1 = CX * 0.02357022603955159f;
  const float CXK2 = CX * 0.01825741858350554f;

  // ---------------- initial weight staging (layer 0) ----------------
  {
    const uint4* src = reinterpret_cast<const uint4*>(&PWg[0]);
    uint4* dst = reinterpret_cast<uint4*>(&sm->pw[0]);
    for (int t = tid; t < (int)(sizeof(PW) / 16); t += NTHREADS) dst[t] = src[t];
  }

  // ---------------- preprocess ----------------
  {
    const int half = ln >> 4;
    const int l16 = ln & 15;
    const int le = e0 + half;
    const int eg = blockIdx.x * TE + le;
    const float* p6 = node_pos + (size_t)eg * 6;
    float ex = p6[1] - p6[0];
    float ey = p6[3] - p6[2];
    float ez = p6[5] - p6[4];
    float r = sqrtf(ex * ex + ey * ey + ez * ez);
    float inv = 1.0f / fmaxf(r, 1e-12f);
    float vx = ex * inv, vy = ey * inv, vz = ez * inv;
    if (l16 == 0) {
      const float s3 = 1.7320508075688772f;
      const float s5 = 2.23606797749979f;
      const float s15 = 3.872983346207417f;
      float* shp = sm->shv[le];
      shp[0] = 1.0f;
      shp[1] = s3 * vx;
      shp[2] = s3 * vy;
      shp[3] = s3 * vz;
      shp[4] = s15 * vx * vz;
      shp[5] = s15 * vx * vy;
      shp[6] = s5 * (vy * vy - 0.5f * (vx * vx + vz * vz));
      shp[7] = s15 * vy * vz;
      shp[8] = 0.5f * s15 * (vz * vz - vx * vx);
      // radial table coords
      const float invD = (float)(TABN - 1) / 4.0f;
      float q = r * invD;
      int idx = (int)q;
      if (idx > TABN - 2) idx = TABN - 2;
      float f = q - (float)idx;
      f = fminf(f, 1.0f);
      sm->ridx[le] = idx;
      sm->rfrac[le] = f;
      // source table coords
      float ba_s = bar_alpha[2 * eg];
      float bq = (ba_s + 6.0f) * ((float)(BAN - 1) / 12.0f);
      bq = fminf(fmaxf(bq, 0.0f), (float)(BAN - 1));
      int bi = (int)bq;
      if (bi > BAN - 2) bi = BAN - 2;
      sm->bidx[le] = bi;
      sm->bfrac[le] = bq - (float)bi;
    }
  }
  if (act) {
    const int geb = blockIdx.x * TE;
    #pragma unroll
    for (int e = 0; e < 2; e++) {
      int le = e0 + e;
      int eg = geb + le;
      float ba_d = bar_alpha[2 * eg + 1];
      #pragma unroll
      for (int ch = 0; ch < 2; ch++) {
        int u = u0 + ch;
        float we = W_embed[u];
        float* xr = sm->X[le][u];
        xr[0] = 0.0f; xr[1] = 0.0f; xr[2] = 0.0f;
        xr[3] = ba_d * we;                        // x0 at phys 3
        xr[4] = 0.0f; xr[5] = 0.0f; xr[6] = 0.0f; xr[7] = 0.0f; xr[8] = 0.0f;
      }
    }
  }
  __syncthreads();

  float xs[2][2][3];

  // ---------------- layers ----------------
  for (int i = 0; i < 3; i++) {
    const PW* cw = &sm->pw[i & 1];
    if (i < 2) {
      const uint4* src = reinterpret_cast<const uint4*>(&PWg[i + 1]);
      uint4* dst = reinterpret_cast<uint4*>(&sm->pw[(i + 1) & 1]);
      for (int t = tid; t < (int)(sizeof(PW) / 16); t += NTHREADS) dst[t] = src[t];
    }

    // ---- wv + h0 from tables (replaces radial MLP + source matvec) ----
    if (act) {
      #pragma unroll
      for (int e = 0; e < 2; e++) {
        int le = e0 + e;
        int idx = sm->ridx[le];
        float f = sm->rfrac[le];
        const float* r0 = &Tabg[i][idx][6 * ln];
        const float* r1 = r0 + 152;
        float2 a0 = *reinterpret_cast<const float2*>(r0);
        float2 a1 = *reinterpret_cast<const float2*>(r0 + 2);
        float2 a2 = *reinterpret_cast<const float2*>(r0 + 4);
        float2 b0 = *reinterpret_cast<const float2*>(r1);
        float2 b1v = *reinterpret_cast<const float2*>(r1 + 2);
        float2 b2 = *reinterpret_cast<const float2*>(r1 + 4);
        float wv00 = a0.x + f * (b0.x - a0.x);
        float wv01 = a0.y + f * (b0.y - a0.y);
        float wv02 = a1.x + f * (b1v.x - a1.x);
        float wv10 = a1.y + f * (b1v.y - a1.y);
        float wv11 = a2.x + f * (b2.x - a2.x);
        float wv12 = a2.y + f * (b2.y - a2.y);
        int bi = sm->bidx[le];
        float bf = sm->bfrac[le];
        const float* h0p = &H0Tabg[i][bi][u0];
        float2 ha = *reinterpret_cast<const float2*>(h0p);
        float2 hb = *reinterpret_cast<const float2*>(h0p + 52);
        float h0x = ha.x + bf * (hb.x - ha.x);   // already * INVS50 * 0.1
        float h0y = ha.y + bf * (hb.y - ha.y);
        float* xr0 = sm->X[le][u0];
        xr0[9]  = h0x * wv00;
        xr0[10] = h0x * wv01;
        xr0[11] = h0x * wv02;
        float* xr1 = sm->X[le][u0 + 1];
        xr1[9]  = h0y * wv10;
        xr1[10] = h0y * wv11;
        xr1[11] = h0y * wv12;
      }
    }
    __syncwarp();

    // ---- stage 3: packed f32x2; pairs (x1,x2)(x3,x0)(x4,x5)(x6,x7)(x8,a0)(a1,a2) ----
    u64 A[2][2][6] = {};
    if (act) {
      #pragma unroll 2
      for (int u = 0; u < MULC; u++) {
        uint2 p0 = *reinterpret_cast<const uint2*>(&cw->P0[u][ln][0]);
        uint2 p1 = *reinterpret_cast<const uint2*>(&cw->P1[u][ln][0]);
        uint2 p2 = *reinterpret_cast<const uint2*>(&cw->P2[u][ln][0]);
        float2 ws0 = h2f(p0.x), ws1 = h2f(p0.y);
        float2 ws2 = h2f(p1.x), l0 = h2f(p1.y);
        float2 l1 = h2f(p2.x), l2 = h2f(p2.y);
        u64 Q0x = pk(ws1.x, ws1.x);
        u64 Q1x = pk(ws1.x, ws0.x);
        u64 Q2x = pk(ws2.x, ws2.x);
        u64 Q3x = pk(ws2.x, l0.x);
        u64 Q4x = pk(l1.x, l2.x);
        u64 Q0y = pk(ws1.y, ws1.y);
        u64 Q1y = pk(ws1.y, ws0.y);
        u64 Q2y = pk(ws2.y, ws2.y);
        u64 Q3y = pk(ws2.y, l0.y);
        u64 Q4y = pk(l1.y, l2.y);
        {
          const ulonglong2* xp = reinterpret_cast<const ulonglong2*>(sm->X[e0][u]);
          ulonglong2 xa = xp[0], xb = xp[1], xc = xp[2];
          fma2(A[0][0][0], xa.x, Q0x);
          fma2(A[0][0][1], xa.y, Q1x);
          fma2(A[0][0][2], xb.x, Q2x);
          fma2(A[0][0][3], xb.y, Q2x);
          fma2(A[0][0][4], xc.x, Q3x);
          fma2(A[0][0][5], xc.y, Q4x);
          fma2(A[0][1][0], xa.x, Q0y);
          fma2(A[0][1][1], xa.y, Q1y);
          fma2(A[0][1][2], xb.x, Q2y);
          fma2(A[0][1][3], xb.y, Q2y);
          fma2(A[0][1][4], xc.x, Q3y);
          fma2(A[0][1][5], xc.y, Q4y);
        }
        {
          const ulonglong2* xp = reinterpret_cast<const ulonglong2*>(sm->X[e1][u]);
          ulonglong2 xa = xp[0], xb = xp[1], xc = xp[2];
          fma2(A[1][0][0], xa.x, Q0x);
          fma2(A[1][0][1], xa.y, Q1x);
          fma2(A[1][0][2], xb.x, Q2x);
          fma2(A[1][0][3], xb.y, Q2x);
          fma2(A[1][0][4], xc.x, Q3x);
          fma2(A[1][0][5], xc.y, Q4x);
          fma2(A[1][1][0], xa.x, Q0y);
          fma2(A[1][1][1], xa.y, Q1y);
          fma2(A[1][1][2], xb.x, Q2y);
          fma2(A[1][1][3], xb.y, Q2y);
          fma2(A[1][1][4], xc.x, Q3y);
          fma2(A[1][1][5], xc.y, Q4y);
        }
      }
    }
    __syncwarp();   // all lanes done reading X
    if (act) {
      #pragma unroll
      for (int e = 0; e < 2; e++) {
        int le = e0 + e;
        const float* shl = sm->shv[le];
        #pragma unroll
        for (int ch = 0; ch < 2; ch++) {
          int u = u0 + ch;
          float ac0, ac1, ac2, ac3, ac4, ac5, ac6, ac7, ac8, b0, b1v, b2;
          upk(ac1, ac2, A[e][ch][0]);
          upk(ac3, ac0, A[e][ch][1]);
          upk(ac4, ac5, A[e][ch][2]);
          upk(ac6, ac7, A[e][ch][3]);
          upk(ac8, b0,  A[e][ch][4]);
          upk(b1v, b2,  A[e][ch][5]);
          float* xr = sm->X[le][u];
          float x0n = CS * INVS50 * ac0 + CXK0 * b0;
          float y1 = CS * INVS50 * ac1 + CXK1 * b1v * shl[1];
          float y2 = CS * INVS50 * ac2 + CXK1 * b1v * shl[2];
          float y3 = CS * INVS50 * ac3 + CXK1 * b1v * shl[3];
          xr[3] = x0n;
          if (i < 2) {
            xr[0] = y1;
            xr[1] = y2;
            xr[2] = y3;
            xr[4] = CS * INVS50 * ac4 + CXK2 * b2 * shl[4];
            xr[5] = CS * INVS50 * ac5 + CXK2 * b2 * shl[5];
            xr[6] = CS * INVS50 * ac6 + CXK2 * b2 * shl[6];
            xr[7] = CS * INVS50 * ac7 + CXK2 * b2 * shl[7];
            xr[8] = CS * INVS50 * ac8 + CXK2 * b2 * shl[8];
          } else {
            xs[e][ch][0] = y1;
            xs[e][ch][1] = y2;
            xs[e][ch][2] = y3;
          }
        }
      }
    }
    __syncwarp();

    // ---- stage 4: gate (packed over ch) ----
    u64 GA0 = 0ull, GA1 = 0ull;
    if (act) {
      #pragma unroll 5
      for (int u = 0; u < MULC; u++) {
        float t0 = sm->X[e0][u][3];
        float t1 = sm->X[e1][u][3];
        float2 wg = ldh2(&cw->Wg[u][u0]);
        u64 WG = pk(wg.x, wg.y);
        u64 T0 = pk(t0, t0), T1 = pk(t1, t1);
        fma2(GA0, T0, WG);
        fma2(GA1, T1, WG);
      }
    }
    float ga[2][2];
    upk(ga[0][0], ga[0][1], GA0);
    upk(ga[1][0], ga[1][1], GA1);
    __syncwarp();
    if (act) {
      #pragma unroll
      for (int e = 0; e < 2; e++) {
        int le = e0 + e;
        #pragma unroll
        for (int ch = 0; ch < 2; ch++) {
          int u = u0 + ch;
          float g = sigmoidf(ga[e][ch] * INVS50);
          if (i < 2) {
            float* xr = sm->X[le][u];
            float4 Af = *reinterpret_cast<const float4*>(xr);
            float4 Bf = *reinterpret_cast<const float4*>(xr + 4);
            float x8 = xr[8];
            float4 qa = make_float4(Af.x * g, Af.y * g, Af.z * g, siluf(Af.w));
            float4 qb = make_float4(Bf.x * g, Bf.y * g, Bf.z * g, Bf.w * g);
            *reinterpret_cast<float4*>(xr)     = qa;
            *reinterpret_cast<float4*>(xr + 4) = qb;
            xr[8] = x8 * g;
          } else {
            xs[e][ch][0] *= g;
            xs[e][ch][1] *= g;
            xs[e][ch][2] *= g;
          }
        }
      }
    }
    __syncthreads();   // protects X reuse + pw double-buffer
  }

  // ---------------- output (from registers) ----------------
  {
    float p[2][3] = {};
    if (act) {
      float wo0 = Wout_g[u0];
      float wo1 = Wout_g[u0 + 1];
      #pragma unroll
      for (int e = 0; e < 2; e++) {
        p[e][0] = xs[e][0][0] * wo0 + xs[e][1][0] * wo1;
        p[e][1] = xs[e][0][1] * wo0 + xs[e][1][1] * wo1;
        p[e][2] = xs[e][0][2] * wo0 + xs[e][1][2] * wo1;
      }
    }
    #pragma unroll
    for (int off = 16; off; off >>= 1) {
      #pragma unroll
      for (int e = 0; e < 2; e++) {
        p[e][0] += __shfl_xor_sync(0xffffffffu, p[e][0], off);
        p[e][1] += __shfl_xor_sync(0xffffffffu, p[e][1], off);
        p[e][2] += __shfl_xor_sync(0xffffffffu, p[e][2], off);
      }
    }
    if (ln == 0) {
      int eg0 = blockIdx.x * TE + e0;
      float* od = out + (size_t)(2 * eg0) * 3;
      od[0] = 0.0f; od[1] = 0.0f; od[2] = 0.0f;
      od[3] = p[0][0] * INVS50;
      od[4] = p[0][1] * INVS50;
      od[5] = p[0][2] * INVS50;
      od[6] = 0.0f; od[7] = 0.0f; od[8] = 0.0f;
      od[9]  = p[1][0] * INVS50;
      od[10] = p[1][1] * INVS50;
      od[11] = p[1][2] * INVS50;
    }
  }
}

extern "C" void kernel_launch(void* const* d_in, const int* in_sizes, int n_in,
                              void* d_out, int out_size) {
  const float* node_pos = (const float*)d_in[0];
  const float* bar_alpha = (const float*)d_in[1];
  const float* W_embed  = (const float*)d_in[2];
  const float* Wsc      = (const float*)d_in[3];
  const float* Wlin1    = (const float*)d_in[4];
  const float* W1       = (const float*)d_in[5];
  const float* b1       = (const float*)d_in[6];
  const float* W2       = (const float*)d_in[7];
  const float* Wlin2    = (const float*)d_in[8];
  const float* Wgate    = (const float*)d_in[9];
  const float* W_out    = (const float*)d_in[10];
  float* out = (float*)d_out;

  pack_kernel<<<dim3(3, 4), 256>>>(Wsc, Wlin2, Wgate);

  size_t tsmem = (size_t)(1104 + 15200 + TPTS * 10 + TPTS * 100) * 4;
  cudaFuncSetAttribute(table_kernel, cudaFuncAttributeMaxDynamicSharedMemorySize, (int)tsmem);
  table_kernel<<<dim3(TABN / TPTS, 3), 256, tsmem>>>(W1, b1, W2);

  h0tab_kernel<<<BAN / 32, 256>>>(Wsc, Wlin1, W_embed);

  int E = in_sizes[0] / 6;
  size_t smem = sizeof(SM);
  cudaFuncSetAttribute(slinky_kernel, cudaFuncAttributeMaxDynamicSharedMemorySize, (int)smem);
  slinky_kernel<<<E / TE, NTHREADS, smem>>>(node_pos, bar_alpha, W_embed, W_out, out);
}

// round 17
// speedup vs baseline: 1.5338x; 1.1577x over previous
#include <cuda_runtime.h>
#include <cuda_fp16.h>

// SlinkyForcePredictor — v16: full slot factorization.
// x_l1[u][k] = beta[u]*sh[k] (induction: separable messages + per-u mixes +
// scalar gate); x_l2 is a DEAD variable (never reaches output). State per
// edge collapses to (alpha[50], beta[50]); per layer only 5 50x50 matvecs.
// sh multiplies once at output. Weights fp32 in smem (no fp16, no packs):
// SD[u]=(a,a,b,b), AD[u]=(a0,a0,a1,a1) pre-duplicated -> fma2 operands direct.
// Radial table Tab2 (p=0,1 only, 104-wide rows) + H0 table from v15.

#define MULC 50
#define TE 32
#define NTHREADS 512
#define TABN 2048
#define TPTS 128
#define BAN 4096

typedef unsigned long long u64;

struct alignas(16) PWf {            // 50000 B per layer
  float WQ[50][25][8];              // {w00x,w00y,wl0x,wl0y,w11x,w11y,wl1x,wl1y}
  float Wg[50][25][2];              // gate weight pair
};
static_assert(sizeof(PWf) % 16 == 0, "");

__device__ PWf PWfg[3];
__device__ __align__(16) float Tab2g[3][TABN][104];   // c = 2u+p, p<2
__device__ __align__(16) float H0Tabg[3][BAN][52];    // h0 * INVS50 * 0.1

struct SM {
  float SD[TE][52][4];    // (alpha,alpha,beta,beta) per u     26624
  float AD[TE][52][4];    // (a0,a0,a1,a1); [0..1] reused x0'  26624
  float shv[TE][4];       // sh[0..3]                           512
  float rfrac[TE];
  float bfrac[TE];
  int   ridx[TE];
  int   bidx[TE];
  PWf pw[2];              // 100000
};

__device__ __forceinline__ float geluf(float x) {
  float x3 = x * x * x;
  float t = tanhf(0.7978845608028654f * (x + 0.044715f * x3));
  return 0.5f * x * (1.0f + t);
}
__device__ __forceinline__ float sigmoidf(float x) { return 1.0f / (1.0f + expf(-x)); }
__device__ __forceinline__ float siluf(float x) { return x * sigmoidf(x); }

__device__ __forceinline__ void upk(float& lo, float& hi, u64 v) {
  asm("mov.b64 {%0, %1}, %2;" : "=f"(lo), "=f"(hi) : "l"(v));
}
__device__ __forceinline__ void fma2(u64& d, u64 a, u64 b) {
  asm("fma.rn.f32x2 %0, %1, %2, %3;" : "=l"(d) : "l"(a), "l"(b), "l"(d));
}

__device__ __forceinline__ float embf(float r, int b) {
  const float step = 4.0f / 11.0f;
  float c = (float)(b + 1) * step;
  float diff = (r - c) / step;
  float up = diff + 1.0f, um = 1.0f - diff;
  float ua = (up > 0.0f) ? expf(-1.0f / up) : 0.0f;
  float ub = (um > 0.0f) ? expf(-1.0f / um) : 0.0f;
  return (1.14136f * 7.3890560989306495f * 3.1622776601683795f) * ua * ub;
}

// ---------------- pre-kernel 1: fp32 weight reorder ----------------
__global__ void pack_kernel(const float* __restrict__ Wsc_g,
                            const float* __restrict__ Wlin2_g,
                            const float* __restrict__ Wgate_g)
{
  const int i = blockIdx.x;
  PWf* p = &PWfg[i];
  const float* wsc = Wsc_g + i * 7500;
  const float* wl2 = Wlin2_g + i * 7500;
  const float* wg  = Wgate_g + i * 2500;
  for (int t = threadIdx.x; t < 50 * 25; t += blockDim.x) {
    int u = t / 25;
    int v2 = t - u * 25;
    int c0 = 2 * v2, c1 = c0 + 1;
    float* q = &p->WQ[u][v2][0];
    q[0] = wsc[0 * 2500 + u * 50 + c0];
    q[1] = wsc[0 * 2500 + u * 50 + c1];
    q[2] = wl2[0 * 2500 + u * 50 + c0];
    q[3] = wl2[0 * 2500 + u * 50 + c1];
    q[4] = wsc[1 * 2500 + u * 50 + c0];
    q[5] = wsc[1 * 2500 + u * 50 + c1];
    q[6] = wl2[1 * 2500 + u * 50 + c0];
    q[7] = wl2[1 * 2500 + u * 50 + c1];
    p->Wg[u][v2][0] = wg[u * 50 + c0];
    p->Wg[u][v2][1] = wg[u * 50 + c1];
  }
}

// ---------------- pre-kernel 2: radial table (p=0,1 only) ----------------
__global__ void table_kernel(const float* __restrict__ W1_g,
                             const float* __restrict__ b1_g,
                             const float* __restrict__ W2_g)
{
  extern __shared__ float ts[];
  float* w1_s  = ts;                       // 1000
  float* b1_s  = ts + 1000;                // 104
  float* w2_s  = ts + 1104;                // 100*100 = 10000
  float* emb_s = ts + 11104;               // TPTS*10
  float* hid_s = ts + 11104 + TPTS * 10;   // TPTS*100

  const int i = blockIdx.y;
  const int p0 = blockIdx.x * TPTS;
  const int t = threadIdx.x;
  const float D = 4.0f / (float)(TABN - 1);

  for (int k = t; k < 1000; k += 256) w1_s[k] = W1_g[i * 1000 + k];
  for (int k = t; k < 100; k += 256) b1_s[k] = b1_g[i * 100 + k];
  for (int k = t; k < 10000; k += 256) {
    int h = k / 100, c = k - h * 100;
    int u = c >> 1, pp = c & 1;
    w2_s[k] = W2_g[i * 75000 + h * 750 + u * 15 + pp];
  }
  for (int k = t; k < TPTS * 10; k += 256) {
    int p = k / 10, b = k - p * 10;
    emb_s[k] = embf((float)(p0 + p) * D, b);
  }
  __syncthreads();
  for (int k = t; k < TPTS * 100; k += 256) {
    int p = k / 100, h = k - p * 100;
    float a = 0.0f;
    #pragma unroll
    for (int b = 0; b < 10; b++) a = fmaf(emb_s[p * 10 + b], w1_s[b * 100 + h], a);
    hid_s[k] = geluf(a * 0.31622776601683794f + b1_s[h]);
  }
  __syncthreads();
  {
    int p = t >> 1;
    int cbase = (t & 1) * 50;
    float acc[50];
    #pragma unroll
    for (int j = 0; j < 50; j++) acc[j] = 0.0f;
    for (int h = 0; h < 100; h++) {
      float hv = hid_s[p * 100 + h];
      #pragma unroll
      for (int j = 0; j < 50; j++) acc[j] = fmaf(hv, w2_s[h * 100 + cbase + j], acc[j]);
    }
    float* row = &Tab2g[i][p0 + p][0];
    #pragma unroll
    for (int j = 0; j < 50; j++) row[cbase + j] = acc[j];
    if (t & 1) { row[100] = 0.0f; row[101] = 0.0f; row[102] = 0.0f; row[103] = 0.0f; }
  }
}

// ---------------- pre-kernel 3: source-chain table (as v15) ----------------
__global__ void h0tab_kernel(const float* __restrict__ Wsc_g,
                             const float* __restrict__ Wlin1_g,
                             const float* __restrict__ W_embed)
{
  __shared__ float s_cur[32][52];
  __shared__ float s_nxt[32][52];
  __shared__ float wl1_s[2500];
  __shared__ float wsc_s[2500];

  const int pl = threadIdx.x >> 3;
  const int vt = threadIdx.x & 7;
  const int p = blockIdx.x * 32 + pl;
  const float ba = -6.0f + 12.0f * (float)p / (float)(BAN - 1);
  const float KS = 0.9238795325112867f * 0.1414213562373095f;
  const float KH = 0.1414213562373095f * 0.1f;

  for (int v = vt; v < 50; v += 8) s_cur[pl][v] = ba * W_embed[v];
  __syncthreads();
  for (int i = 0; i < 3; i++) {
    for (int k = threadIdx.x; k < 2500; k += 256) {
      wl1_s[k] = Wlin1_g[i * 7500 + k];
      wsc_s[k] = Wsc_g[i * 7500 + k];
    }
    __syncthreads();
    for (int v = vt; v < 50; v += 8) {
      float h = 0.0f, sc = 0.0f;
      #pragma unroll 10
      for (int t = 0; t < 50; t++) {
        float sv = s_cur[pl][t];
        h  = fmaf(sv, wl1_s[t * 50 + v], h);
        sc = fmaf(sv, wsc_s[t * 50 + v], sc);
      }
      H0Tabg[i][p][v] = KH * h;
      s_nxt[pl][v] = siluf(KS * sc);
    }
    __syncthreads();
    for (int v = vt; v < 50; v += 8) s_cur[pl][v] = s_nxt[pl][v];
    __syncthreads();
  }
}

// ---------------- main kernel ----------------
__global__ __launch_bounds__(NTHREADS, 1)
void slinky_kernel(const float* __restrict__ node_pos,
                   const float* __restrict__ bar_alpha,
                   const float* __restrict__ W_embed,
                   const float* __restrict__ Wout_g,
                   float* __restrict__ out)
{
  extern __shared__ __align__(16) float smem_raw[];
  SM* sm = reinterpret_cast<SM*>(smem_raw);

  const int tid = threadIdx.x;
  const int w   = tid >> 5;
  const int ln  = tid & 31;
  const int e0  = 2 * w;
  const int e1  = 2 * w + 1;
  const bool act = (ln < 25);
  const int u0 = 2 * ln;

  const float INVS50 = 0.1414213562373095f;
  const float CS = 0.9238795325112867f;
  const float CX = 0.3826834323650898f;
  const float K1 = CS * INVS50;
  const float CXK0 = CX * 0.05773502691896258f;
  const float CXK1 = CX * 0.02357022603955159f;

  // stage layer-0 weights
  {
    const uint4* src = reinterpret_cast<const uint4*>(&PWfg[0]);
    uint4* dst = reinterpret_cast<uint4*>(&sm->pw[0]);
    for (int t = tid; t < (int)(sizeof(PWf) / 16); t += NTHREADS) dst[t] = src[t];
  }

  // ---------------- preprocess ----------------
  {
    const int half = ln >> 4;
    const int l16 = ln & 15;
    const int le = e0 + half;
    const int eg = blockIdx.x * TE + le;
    if (l16 == 0) {
      const float* p6 = node_pos + (size_t)eg * 6;
      float ex = p6[1] - p6[0];
      float ey = p6[3] - p6[2];
      float ez = p6[5] - p6[4];
      float r = sqrtf(ex * ex + ey * ey + ez * ez);
      float inv = 1.0f / fmaxf(r, 1e-12f);
      const float s3 = 1.7320508075688772f;
      float* shp = sm->shv[le];
      shp[0] = 1.0f;
      shp[1] = s3 * ex * inv;
      shp[2] = s3 * ey * inv;
      shp[3] = s3 * ez * inv;
      const float invD = (float)(TABN - 1) / 4.0f;
      float q = r * invD;
      int idx = (int)q;
      if (idx > TABN - 2) idx = TABN - 2;
      float f = fminf(q - (float)idx, 1.0f);
      sm->ridx[le] = idx;
      sm->rfrac[le] = f;
      float ba_s = bar_alpha[2 * eg];
      float bq = (ba_s + 6.0f) * ((float)(BAN - 1) / 12.0f);
      bq = fminf(fmaxf(bq, 0.0f), (float)(BAN - 1));
      int bi = (int)bq;
      if (bi > BAN - 2) bi = BAN - 2;
      sm->bidx[le] = bi;
      sm->bfrac[le] = bq - (float)bi;
    }
  }
  if (act) {
    const int geb = blockIdx.x * TE;
    #pragma unroll
    for (int e = 0; e < 2; e++) {
      int le = e0 + e;
      float ba_d = bar_alpha[2 * (geb + le) + 1];
      #pragma unroll
      for (int ch = 0; ch < 2; ch++) {
        int u = u0 + ch;
        float a0 = ba_d * W_embed[u];
        *reinterpret_cast<float4*>(&sm->SD[le][u][0]) = make_float4(a0, a0, 0.0f, 0.0f);
      }
    }
  }
  __syncthreads();

  float bfin[2][2];   // final beta for own channels

  // ---------------- layers ----------------
  for (int i = 0; i < 3; i++) {
    const PWf* cw = &sm->pw[i & 1];
    if (i < 2) {
      const uint4* src = reinterpret_cast<const uint4*>(&PWfg[i + 1]);
      uint4* dst = reinterpret_cast<uint4*>(&sm->pw[(i + 1) & 1]);
      for (int t = tid; t < (int)(sizeof(PWf) / 16); t += NTHREADS) dst[t] = src[t];
    }

    // ---- a-values from tables ----
    if (act) {
      #pragma unroll
      for (int e = 0; e < 2; e++) {
        int le = e0 + e;
        int idx = sm->ridx[le];
        float f = sm->rfrac[le];
        float4 wa = *reinterpret_cast<const float4*>(&Tab2g[i][idx][4 * ln]);
        float4 wb = *reinterpret_cast<const float4*>(&Tab2g[i][idx + 1][4 * ln]);
        float wv00 = wa.x + f * (wb.x - wa.x);   // u0 p0
        float wv01 = wa.y + f * (wb.y - wa.y);   // u0 p1
        float wv10 = wa.z + f * (wb.z - wa.z);   // u1 p0
        float wv11 = wa.w + f * (wb.w - wa.w);   // u1 p1
        int bi = sm->bidx[le];
        float bf = sm->bfrac[le];
        const float* h0p = &H0Tabg[i][bi][u0];
        float2 ha = *reinterpret_cast<const float2*>(h0p);
        float2 hb = *reinterpret_cast<const float2*>(h0p + 52);
        float h0x = ha.x + bf * (hb.x - ha.x);
        float h0y = ha.y + bf * (hb.y - ha.y);
        float a00 = h0x * wv00, a10 = h0x * wv01;
        float a01 = h0y * wv10, a11 = h0y * wv11;
        *reinterpret_cast<float4*>(&sm->AD[le][u0][0])     = make_float4(a00, a00, a10, a10);
        *reinterpret_cast<float4*>(&sm->AD[le][u0 + 1][0]) = make_float4(a01, a01, a11, a11);
      }
    }
    __syncwarp();

    // ---- matvec: 4 accumulators per edge ----
    u64 A0[2] = {}, A1[2] = {}, A2[2] = {}, A3[2] = {};
    if (act) {
      #pragma unroll 2
      for (int u = 0; u < MULC; u++) {
        const ulonglong2* wq = reinterpret_cast<const ulonglong2*>(&cw->WQ[u][ln][0]);
        ulonglong2 w1 = wq[0];   // (wsc0 pair, wl20 pair)
        ulonglong2 w2 = wq[1];   // (wsc1 pair, wl21 pair)
        {
          ulonglong2 sd = *reinterpret_cast<const ulonglong2*>(&sm->SD[e0][u][0]);
          ulonglong2 ad = *reinterpret_cast<const ulonglong2*>(&sm->AD[e0][u][0]);
          fma2(A0[0], sd.x, w1.x);
          fma2(A1[0], ad.x, w1.y);
          fma2(A2[0], sd.y, w2.x);
          fma2(A3[0], ad.y, w2.y);
        }
        {
          ulonglong2 sd = *reinterpret_cast<const ulonglong2*>(&sm->SD[e1][u][0]);
          ulonglong2 ad = *reinterpret_cast<const ulonglong2*>(&sm->AD[e1][u][0]);
          fma2(A0[1], sd.x, w1.x);
          fma2(A1[1], ad.x, w1.y);
          fma2(A2[1], sd.y, w2.x);
          fma2(A3[1], ad.y, w2.y);
        }
      }
    }
    __syncwarp();   // AD reads done (this warp)

    // ---- epilogue 1: x0', y; write x0' dup into AD[..][0..1] ----
    float yv[2][2], x0v[2][2];
    if (act) {
      #pragma unroll
      for (int e = 0; e < 2; e++) {
        int le = e0 + e;
        float t0x, t0y, t1x, t1y, t2x, t2y, t3x, t3y;
        upk(t0x, t0y, A0[e]);
        upk(t1x, t1y, A1[e]);
        upk(t2x, t2y, A2[e]);
        upk(t3x, t3y, A3[e]);
        float xx = K1 * t0x + CXK0 * t1x;
        float xy = K1 * t0y + CXK0 * t1y;
        x0v[e][0] = xx; x0v[e][1] = xy;
        yv[e][0] = K1 * t2x + CXK1 * t3x;
        yv[e][1] = K1 * t2y + CXK1 * t3y;
        *reinterpret_cast<float2*>(&sm->AD[le][u0][0])     = make_float2(xx, xx);
        *reinterpret_cast<float2*>(&sm->AD[le][u0 + 1][0]) = make_float2(xy, xy);
      }
    }
    __syncwarp();

    // ---- gate matvec ----
    u64 G[2] = {};
    if (act) {
      #pragma unroll 4
      for (int u = 0; u < MULC; u++) {
        u64 wg = *reinterpret_cast<const u64*>(&cw->Wg[u][ln][0]);
        u64 xd0 = *reinterpret_cast<const u64*>(&sm->AD[e0][u][0]);
        u64 xd1 = *reinterpret_cast<const u64*>(&sm->AD[e1][u][0]);
        fma2(G[0], xd0, wg);
        fma2(G[1], xd1, wg);
      }
    }
    __syncwarp();

    // ---- apply ----
    if (act) {
      #pragma unroll
      for (int e = 0; e < 2; e++) {
        int le = e0 + e;
        float gx, gy;
        upk(gx, gy, G[e]);
        float g0 = sigmoidf(gx * INVS50);
        float g1 = sigmoidf(gy * INVS50);
        float b0 = yv[e][0] * g0;
        float b1 = yv[e][1] * g1;
        if (i < 2) {
          float al0 = siluf(x0v[e][0]);
          float al1 = siluf(x0v[e][1]);
          *reinterpret_cast<float4*>(&sm->SD[le][u0][0])     = make_float4(al0, al0, b0, b0);
          *reinterpret_cast<float4*>(&sm->SD[le][u0 + 1][0]) = make_float4(al1, al1, b1, b1);
        } else {
          bfin[e][0] = b0;
          bfin[e][1] = b1;
        }
      }
    }
    if (i < 2) __syncthreads();   // pw double-buffer + SD/AD visibility
  }

  // ---------------- output ----------------
  {
    float S[2] = {0.0f, 0.0f};
    if (act) {
      float wo0 = Wout_g[u0];
      float wo1 = Wout_g[u0 + 1];
      S[0] = bfin[0][0] * wo0 + bfin[0][1] * wo1;
      S[1] = bfin[1][0] * wo0 + bfin[1][1] * wo1;
    }
    #pragma unroll
    for (int off = 16; off; off >>= 1) {
      S[0] += __shfl_xor_sync(0xffffffffu, S[0], off);
      S[1] += __shfl_xor_sync(0xffffffffu, S[1], off);
    }
    if (ln == 0) {
      int eg0 = blockIdx.x * TE + e0;
      const float* sh0 = sm->shv[e0];
      const float* sh1 = sm->shv[e1];
      float* od = out + (size_t)(2 * eg0) * 3;
      od[0] = 0.0f; od[1] = 0.0f; od[2] = 0.0f;
      od[3] = S[0] * INVS50 * sh0[1];
      od[4] = S[0] * INVS50 * sh0[2];
      od[5] = S[0] * INVS50 * sh0[3];
      od[6] = 0.0f; od[7] = 0.0f; od[8] = 0.0f;
      od[9]  = S[1] * INVS50 * sh1[1];
      od[10] = S[1] * INVS50 * sh1[2];
      od[11] = S[1] * INVS50 * sh1[3];
    }
  }
}

extern "C" void kernel_launch(void* const* d_in, const int* in_sizes, int n_in,
                              void* d_out, int out_size) {
  const float* node_pos = (const float*)d_in[0];
  const float* bar_alpha = (const float*)d_in[1];
  const float* W_embed  = (const float*)d_in[2];
  const float* Wsc      = (const float*)d_in[3];
  const float* Wlin1    = (const float*)d_in[4];
  const float* W1       = (const float*)d_in[5];
  const float* b1       = (const float*)d_in[6];
  const float* W2       = (const float*)d_in[7];
  const float* Wlin2    = (const float*)d_in[8];
  const float* Wgate    = (const float*)d_in[9];
  const float* W_out    = (const float*)d_in[10];
  float* out = (float*)d_out;

  pack_kernel<<<3, 256>>>(Wsc, Wlin2, Wgate);

  size_t tsmem = (size_t)(11104 + TPTS * 10 + TPTS * 100) * 4;
  cudaFuncSetAttribute(table_kernel, cudaFuncAttributeMaxDynamicSharedMemorySize, (int)tsmem);
  table_kernel<<<dim3(TABN / TPTS, 3), 256, tsmem>>>(W1, b1, W2);

  h0tab_kernel<<<BAN / 32, 256>>>(Wsc, Wlin1, W_embed);

  int E = in_sizes[0] / 6;
  size_t smem = sizeof(SM);
  cudaFuncSetAttribute(slinky_kernel, cudaFuncAttributeMaxDynamicSharedMemorySize, (int)smem);
  slinky_kernel<<<E / TE, NTHREADS, smem>>>(node_pos, bar_alpha, W_embed, W_out, out);
}